// round 14
// baseline (speedup 1.0000x reference)
#include <cuda_runtime.h>
#include <cuda_fp16.h>
#include <cstdint>

#define BATCH 2
#define SEQ 2048
#define DIM 2048
#define NH 32
#define NKV 8
#define HD 64
#define MTOT (BATCH * SEQ)
#define QSCALE 0.18033688011112042f

extern __shared__ char dsmem[];

// Scratch (no cudaMalloc allowed)
__device__ __half g_xh[MTOT * DIM];
__device__ __half g_qp[MTOT * NH * HD];
__device__ __half g_kp[MTOT * NKV * HD];
__device__ __half g_qh[MTOT * NH * HD];
__device__ __half g_kh[MTOT * NKV * HD];
__device__ __half g_vh[MTOT * NKV * HD];
__device__ __half g_oh[MTOT * NH * HD];
__device__ __half g_wqkvt[3072 * DIM];
__device__ __half g_wot[DIM * DIM];

// ---------------------------------------------------------------------------
// helpers
// ---------------------------------------------------------------------------
__device__ __forceinline__ uint32_t smem_u32(const void* p) {
    uint32_t a;
    asm("{ .reg .u64 t; cvta.to.shared.u64 t, %1; cvt.u32.u64 %0, t; }" : "=r"(a) : "l"(p));
    return a;
}

__device__ __forceinline__ void cpa16(uint32_t dst, const void* src) {
    asm volatile("cp.async.cg.shared.global [%0], [%1], 16;" :: "r"(dst), "l"(src) : "memory");
}
#define CP_COMMIT() asm volatile("cp.async.commit_group;" ::: "memory")
#define CP_WAIT1()  asm volatile("cp.async.wait_group 1;" ::: "memory")

__device__ __forceinline__ void ldm_x4(uint32_t r[4], uint32_t addr) {
    asm volatile("ldmatrix.sync.aligned.m8n8.x4.shared.b16 {%0,%1,%2,%3}, [%4];"
                 : "=r"(r[0]), "=r"(r[1]), "=r"(r[2]), "=r"(r[3]) : "r"(addr));
}
__device__ __forceinline__ void ldm_x4t(uint32_t r[4], uint32_t addr) {
    asm volatile("ldmatrix.sync.aligned.m8n8.x4.trans.shared.b16 {%0,%1,%2,%3}, [%4];"
                 : "=r"(r[0]), "=r"(r[1]), "=r"(r[2]), "=r"(r[3]) : "r"(addr));
}

__device__ __forceinline__ void mma_f16(float c[4], const uint32_t a[4],
                                        uint32_t b0, uint32_t b1) {
    asm volatile(
        "mma.sync.aligned.m16n8k16.row.col.f32.f16.f16.f32 "
        "{%0,%1,%2,%3}, {%4,%5,%6,%7}, {%8,%9}, {%0,%1,%2,%3};"
        : "+f"(c[0]), "+f"(c[1]), "+f"(c[2]), "+f"(c[3])
        : "r"(a[0]), "r"(a[1]), "r"(a[2]), "r"(a[3]), "r"(b0), "r"(b1));
}

__device__ __forceinline__ uint32_t ex2h2(float x, float y) {
    __half2 d = __floats2half2_rn(x, y);
    uint32_t e;
    asm("ex2.approx.f16x2 %0, %1;" : "=r"(e) : "r"(*(uint32_t*)&d));
    return e;
}

__device__ __forceinline__ void store2(float* C, size_t off, float x, float y) {
    *(float2*)&C[off] = make_float2(x, y);
}
__device__ __forceinline__ void store2(__half* C, size_t off, float x, float y) {
    *(__half2*)&C[off] = __floats2half2_rn(x, y);
}

// ---------------------------------------------------------------------------
// Fused prep: f2h of x, QKV weight transpose, Wo transpose
// ---------------------------------------------------------------------------
#define NB_F2H (MTOT * DIM / 1024)

__global__ __launch_bounds__(256) void prep_kernel(
    const float* __restrict__ x, __half* __restrict__ xh,
    const float* __restrict__ Wq, const float* __restrict__ Wk,
    const float* __restrict__ Wv, __half* __restrict__ wqkvt,
    const float* __restrict__ Wo, __half* __restrict__ wot)
{
    __shared__ float tbuf[32][33];
    const int bid = blockIdx.x;
    const int tid = threadIdx.x;

    if (bid < NB_F2H) {
        int i = (bid * 256 + tid) * 4;
        float4 v = *(const float4*)&x[i];
        *(__half2*)&xh[i]     = __floats2half2_rn(v.x, v.y);
        *(__half2*)&xh[i + 2] = __floats2half2_rn(v.z, v.w);
        return;
    }

    const int tx = tid & 31, ty = tid >> 5;
    const float* src; __half* dst;
    int srcN, nloc, n0, k0, dstK;

    if (bid < NB_F2H + 6144) {
        const int tb = bid - NB_F2H;
        n0 = (tb % 96) * 32;
        k0 = (tb / 96) * 32;
        if (n0 < 2048)      { src = Wq; srcN = 2048; nloc = n0; }
        else if (n0 < 2560) { src = Wk; srcN = 512;  nloc = n0 - 2048; }
        else                { src = Wv; srcN = 512;  nloc = n0 - 2560; }
        dst = wqkvt; dstK = DIM;
    } else {
        const int tb = bid - NB_F2H - 6144;
        n0 = (tb % 64) * 32;
        k0 = (tb / 64) * 32;
        src = Wo; srcN = DIM; nloc = n0;
        dst = wot; dstK = DIM;
    }

#pragma unroll
    for (int r = ty; r < 32; r += 8)
        tbuf[r][tx] = src[(size_t)(k0 + r) * srcN + nloc + tx];
    __syncthreads();
#pragma unroll
    for (int r = ty; r < 32; r += 8)
        dst[(size_t)(n0 + r) * dstK + k0 + tx] = __float2half(tbuf[tx][r]);
}

// ---------------------------------------------------------------------------
// GEMM core (round-12 proven config: 128x128, BK=32, 3-stage, 2 CTAs/SM)
// ---------------------------------------------------------------------------
#define GPAD 40
#define GBUF (128 * GPAD)
#define STAGES 3
#define HGEMM_SMEM (2 * STAGES * GBUF * 2)   // 61440 B

struct GemmAcc { float a[4][4][4]; };

template <typename EPI>
__device__ __forceinline__ void hgemm_core(
    const __half* Ag0, const __half* Bg0, int K, EPI epi)
{
    __half* Asm = (__half*)dsmem;
    __half* Bsm = Asm + STAGES * GBUF;
    const uint32_t sA = smem_u32(Asm), sB = smem_u32(Bsm);

    const int tid = threadIdx.x, lane = tid & 31, warp = tid >> 5;
    const int wm = warp & 1, wn = warp >> 1;
    const int g = lane >> 2, t = lane & 3;
    const int srow = tid >> 1, sk = (tid & 1) * 16;

    const int ra = (lane & 7) + 8 * ((lane >> 3) & 1);
    const int ca = 8 * (lane >> 4);
    const int rb = (lane & 7) + 8 * (lane >> 4);
    const int cb = 8 * ((lane >> 3) & 1);

    const __half* Ag = Ag0 + (size_t)srow * K + sk;
    const __half* Bg = Bg0 + (size_t)srow * K + sk;
    const uint32_t stOff = (uint32_t)(srow * GPAD + sk) * 2;

    GemmAcc acc;
#pragma unroll
    for (int i = 0; i < 4; i++)
#pragma unroll
        for (int j = 0; j < 4; j++)
#pragma unroll
            for (int c = 0; c < 4; c++) acc.a[i][j][c] = 0.f;

    const int KT = K / 32;
#pragma unroll
    for (int p = 0; p < 2; p++) {
        uint32_t da = sA + p * GBUF * 2 + stOff;
        uint32_t db = sB + p * GBUF * 2 + stOff;
        cpa16(da, Ag + p * 32);  cpa16(da + 16, Ag + p * 32 + 8);
        cpa16(db, Bg + p * 32);  cpa16(db + 16, Bg + p * 32 + 8);
        CP_COMMIT();
    }

    for (int it = 0; it < KT; it++) {
        CP_WAIT1();
        __syncthreads();
        if (it + 2 < KT) {
            const int st = (it + 2) % STAGES;
            uint32_t da = sA + st * GBUF * 2 + stOff;
            uint32_t db = sB + st * GBUF * 2 + stOff;
            cpa16(da, Ag + (it + 2) * 32);  cpa16(da + 16, Ag + (it + 2) * 32 + 8);
            cpa16(db, Bg + (it + 2) * 32);  cpa16(db + 16, Bg + (it + 2) * 32 + 8);
        }
        CP_COMMIT();

        const uint32_t bA = sA + (it % STAGES) * GBUF * 2;
        const uint32_t bB = sB + (it % STAGES) * GBUF * 2;
#pragma unroll
        for (int ks = 0; ks < 2; ks++) {
            const int k0 = ks * 16;
            uint32_t af[4][4];
#pragma unroll
            for (int mt = 0; mt < 4; mt++)
                ldm_x4(af[mt], bA + ((wm * 64 + mt * 16 + ra) * GPAD + k0 + ca) * 2);
#pragma unroll
            for (int bp = 0; bp < 2; bp++) {
                uint32_t b4[4];
                ldm_x4(b4, bB + ((wn * 32 + bp * 16 + rb) * GPAD + k0 + cb) * 2);
#pragma unroll
                for (int mt = 0; mt < 4; mt++) {
                    mma_f16(acc.a[mt][2 * bp],     af[mt], b4[0], b4[1]);
                    mma_f16(acc.a[mt][2 * bp + 1], af[mt], b4[2], b4[3]);
                }
            }
        }
    }
    epi(acc, wm, wn, g, t);
}

// QKV fused projection
__global__ __launch_bounds__(256, 2) void hgemm_qkv(
    const __half* __restrict__ A, const __half* __restrict__ Bt,
    __half* __restrict__ Q, __half* __restrict__ Kc, __half* __restrict__ V)
{
    const int bx = blockIdx.x, by = blockIdx.y;
    __half* Cp; int colbase, stride;
    if (bx < 16)      { Cp = Q;  colbase = bx * 128;        stride = 2048; }
    else if (bx < 20) { Cp = Kc; colbase = (bx - 16) * 128; stride = 512;  }
    else              { Cp = V;  colbase = (bx - 20) * 128; stride = 512;  }
    hgemm_core(A + (size_t)(by * 128) * DIM, Bt + (size_t)(bx * 128) * DIM, DIM,
        [&](const GemmAcc& acc, int wm, int wn, int g, int t) {
#pragma unroll
            for (int mt = 0; mt < 4; mt++) {
                const int row = by * 128 + wm * 64 + mt * 16 + g;
#pragma unroll
                for (int nt = 0; nt < 4; nt++) {
                    const int col = colbase + wn * 32 + nt * 8 + 2 * t;
                    store2(Cp, (size_t)row * stride + col,
                           acc.a[mt][nt][0], acc.a[mt][nt][1]);
                    store2(Cp, (size_t)(row + 8) * stride + col,
                           acc.a[mt][nt][2], acc.a[mt][nt][3]);
                }
            }
        });
}

__global__ __launch_bounds__(256, 2) void hgemm_f(
    const __half* __restrict__ A, const __half* __restrict__ Bt,
    float* __restrict__ C, int N, int K)
{
    const int bx = blockIdx.x, by = blockIdx.y;
    hgemm_core(A + (size_t)(by * 128) * K, Bt + (size_t)(bx * 128) * K, K,
        [&](const GemmAcc& acc, int wm, int wn, int g, int t) {
#pragma unroll
            for (int mt = 0; mt < 4; mt++) {
                const int row = by * 128 + wm * 64 + mt * 16 + g;
#pragma unroll
                for (int nt = 0; nt < 4; nt++) {
                    const int col = bx * 128 + wn * 32 + nt * 8 + 2 * t;
                    store2(C, (size_t)row * N + col, acc.a[mt][nt][0], acc.a[mt][nt][1]);
                    store2(C, (size_t)(row + 8) * N + col, acc.a[mt][nt][2], acc.a[mt][nt][3]);
                }
            }
        });
}

// ---------------------------------------------------------------------------
// Fused RoPE for Q and K
// ---------------------------------------------------------------------------
#define QTOT4 (MTOT * NH * 8)
#define KTOT4 (MTOT * NKV * 8)

__global__ void rope_fused(const __half* __restrict__ qin, __half* __restrict__ qout,
                           const __half* __restrict__ kin, __half* __restrict__ kout,
                           const float* __restrict__ cs, const float* __restrict__ sn)
{
    int idx = blockIdx.x * blockDim.x + threadIdx.x;
    const __half* in; __half* out;
    int nheads; float scale;
    if (idx < QTOT4) {
        in = qin; out = qout; nheads = NH; scale = QSCALE;
    } else {
        idx -= QTOT4;
        if (idx >= KTOT4) return;
        in = kin; out = kout; nheads = NKV; scale = 1.0f;
    }
    const int d4 = (idx & 7) * 4;
    const int rest = idx >> 3;
    const int s = (rest / nheads) % SEQ;
    const size_t base = (size_t)rest * HD;
    uint2 lo2 = *(const uint2*)&in[base + d4];
    uint2 hi2 = *(const uint2*)&in[base + d4 + 32];
    const __half2* lh = (const __half2*)&lo2;
    const __half2* hh = (const __half2*)&hi2;
    float2 l01 = __half22float2(lh[0]), l23 = __half22float2(lh[1]);
    float2 h01 = __half22float2(hh[0]), h23 = __half22float2(hh[1]);
    float4 c0 = *(const float4*)&cs[s * HD + d4];
    float4 s0 = *(const float4*)&sn[s * HD + d4];
    float4 c1 = *(const float4*)&cs[s * HD + d4 + 32];
    float4 s1 = *(const float4*)&sn[s * HD + d4 + 32];
    *(__half2*)&out[base + d4] = __floats2half2_rn(
        (l01.x * c0.x - h01.x * s0.x) * scale, (l01.y * c0.y - h01.y * s0.y) * scale);
    *(__half2*)&out[base + d4 + 2] = __floats2half2_rn(
        (l23.x * c0.z - h23.x * s0.z) * scale, (l23.y * c0.w - h23.y * s0.w) * scale);
    *(__half2*)&out[base + d4 + 32] = __floats2half2_rn(
        (h01.x * c1.x + l01.x * s1.x) * scale, (h01.y * c1.y + l01.y * s1.y) * scale);
    *(__half2*)&out[base + d4 + 34] = __floats2half2_rn(
        (h23.x * c1.z + l23.x * s1.z) * scale, (h23.y * c1.w + l23.y * s1.w) * scale);
}

// ---------------------------------------------------------------------------
// fp16 flash attention: MMA row sums + LPT + fully-masked-chunk skip.
// ---------------------------------------------------------------------------
#define APAD 72
#define KVBUF (64 * APAD)
#define ATTN_SMEM ((128 + 3 * 64 + 3 * 64) * APAD * 2)   // 73728 B
#define ONESH2 0x3C003C00u

__global__ __launch_bounds__(256) void attn_h(
    const __half* __restrict__ Qg, const __half* __restrict__ Kg,
    const __half* __restrict__ Vg, __half* __restrict__ Og)
{
    __half* Qs = (__half*)dsmem;
    __half* Ks = Qs + 128 * APAD;
    __half* Vs = Ks + 3 * KVBUF;
    const uint32_t sQ = smem_u32(Qs), sK = smem_u32(Ks), sV = smem_u32(Vs);

    const int lin = blockIdx.x;
    const int qb = (SEQ / 128 - 1) - (lin >> 6);
    const int h = lin & 31;
    const int b = (lin >> 5) & 1;
    const int kvh = h >> 2;
    const int tid = threadIdx.x;
    const int warp = tid >> 5, lane = tid & 31;
    const int g = lane >> 2, t = lane & 3;
    const int rowbase = warp * 16;

    const int ra = (lane & 7) + 8 * ((lane >> 3) & 1);
    const int ca = 8 * (lane >> 4);
    const int rb = (lane & 7) + 8 * (lane >> 4);
    const int cb = 8 * ((lane >> 3) & 1);

    const int nchunks = 2 * (qb + 1);
    const int svrow = tid >> 2;
    const int svc   = (tid & 3) * 16;
    const uint32_t kvOff = (uint32_t)(svrow * APAD + svc) * 2;
    const size_t gstride = (size_t)64 * NKV * HD;
    const __half* Kgp = Kg + (((size_t)b * SEQ + svrow) * NKV + kvh) * HD + svc;
    const __half* Vgp = Vg + (((size_t)b * SEQ + svrow) * NKV + kvh) * HD + svc;

#pragma unroll
    for (int p = 0; p < 2; p++) {
        uint32_t dk = sK + p * KVBUF * 2 + kvOff;
        uint32_t dv = sV + p * KVBUF * 2 + kvOff;
        cpa16(dk, Kgp + p * gstride);  cpa16(dk + 16, Kgp + p * gstride + 8);
        cpa16(dv, Vgp + p * gstride);  cpa16(dv + 16, Vgp + p * gstride + 8);
        CP_COMMIT();
    }

    {
        const int row = tid & 127;
        const int c0 = (tid >> 7) * 32;
        const __half* src = &Qg[(((size_t)b * SEQ + qb * 128 + row) * NH + h) * HD + c0];
        uint32_t d = sQ + (row * APAD + c0) * 2;
#pragma unroll
        for (int i = 0; i < 4; i++) {
            uint4 v = *(const uint4*)(src + 8 * i);
            asm volatile("st.shared.v4.b32 [%0], {%1,%2,%3,%4};" :: "r"(d + 16 * i),
                         "r"(v.x), "r"(v.y), "r"(v.z), "r"(v.w) : "memory");
        }
    }
    __syncthreads();

    uint32_t qf[4][4];
#pragma unroll
    for (int kt = 0; kt < 4; kt++)
        ldm_x4(qf[kt], sQ + ((rowbase + ra) * APAD + kt * 16 + ca) * 2);

    float m0r = -1e30f, m1r = -1e30f, l0r = 0.f, l1r = 0.f;
    float of[8][4];
#pragma unroll
    for (int nt = 0; nt < 8; nt++)
#pragma unroll
        for (int c = 0; c < 4; c++) of[nt][c] = 0.f;

    // highest q-row this warp owns (global)
    const int warp_qmax = qb * 128 + rowbase + 15;

    for (int kc = 0; kc < nchunks; kc++) {
        CP_WAIT1();
        __syncthreads();
        if (kc + 2 < nchunks) {
            const int st = (kc + 2) % 3;
            uint32_t dk = sK + st * KVBUF * 2 + kvOff;
            uint32_t dv = sV + st * KVBUF * 2 + kvOff;
            cpa16(dk, Kgp + (size_t)(kc + 2) * gstride);
            cpa16(dk + 16, Kgp + (size_t)(kc + 2) * gstride + 8);
            cpa16(dv, Vgp + (size_t)(kc + 2) * gstride);
            cpa16(dv + 16, Vgp + (size_t)(kc + 2) * gstride + 8);
        }
        CP_COMMIT();

        // entire chunk masked for this warp's rows -> skip compute
        if (kc * 64 > warp_qmax) continue;

        const uint32_t bK = sK + (kc % 3) * KVBUF * 2;
        const uint32_t bV = sV + (kc % 3) * KVBUF * 2;

        float sf[8][4];
#pragma unroll
        for (int nt = 0; nt < 8; nt++)
#pragma unroll
            for (int c = 0; c < 4; c++) sf[nt][c] = 0.f;

#pragma unroll
        for (int kt = 0; kt < 4; kt++) {
#pragma unroll
            for (int bp = 0; bp < 4; bp++) {
                uint32_t b4[4];
                ldm_x4(b4, bK + ((bp * 16 + rb) * APAD + kt * 16 + cb) * 2);
                mma_f16(sf[2 * bp],     qf[kt], b4[0], b4[1]);
                mma_f16(sf[2 * bp + 1], qf[kt], b4[2], b4[3]);
            }
        }

        const int qr0 = qb * 128 + rowbase + g;
        const int qr1 = qr0 + 8;
        if (kc * 64 + 63 > qr0) {
#pragma unroll
            for (int nt = 0; nt < 8; nt++) {
                const int kv0 = kc * 64 + nt * 8 + 2 * t;
                if (kv0 > qr0)     sf[nt][0] = -1e30f;
                if (kv0 + 1 > qr0) sf[nt][1] = -1e30f;
                if (kv0 > qr1)     sf[nt][2] = -1e30f;
                if (kv0 + 1 > qr1) sf[nt][3] = -1e30f;
            }
        }

        float mx0 = -1e30f, mx1 = -1e30f;
#pragma unroll
        for (int nt = 0; nt < 8; nt++) {
            mx0 = fmaxf(mx0, fmaxf(sf[nt][0], sf[nt][1]));
            mx1 = fmaxf(mx1, fmaxf(sf[nt][2], sf[nt][3]));
        }
        mx0 = fmaxf(mx0, __shfl_xor_sync(0xffffffffu, mx0, 1));
        mx0 = fmaxf(mx0, __shfl_xor_sync(0xffffffffu, mx0, 2));
        mx1 = fmaxf(mx1, __shfl_xor_sync(0xffffffffu, mx1, 1));
        mx1 = fmaxf(mx1, __shfl_xor_sync(0xffffffffu, mx1, 2));

        const float mn0 = fmaxf(m0r, mx0);
        const float mn1 = fmaxf(m1r, mx1);
        const float al0 = exp2f(m0r - mn0);
        const float al1 = exp2f(m1r - mn1);
        m0r = mn0; m1r = mn1;

        uint32_t ph[8][2];
#pragma unroll
        for (int nt = 0; nt < 8; nt++) {
            ph[nt][0] = ex2h2(sf[nt][0] - mn0, sf[nt][1] - mn0);
            ph[nt][1] = ex2h2(sf[nt][2] - mn1, sf[nt][3] - mn1);
        }

#pragma unroll
        for (int nt = 0; nt < 8; nt++) {
            of[nt][0] *= al0; of[nt][1] *= al0;
            of[nt][2] *= al1; of[nt][3] *= al1;
        }

        float lsum[4] = {0.f, 0.f, 0.f, 0.f};
#pragma unroll
        for (int j = 0; j < 4; j++) {
            uint32_t pa[4] = { ph[2 * j][0], ph[2 * j][1],
                               ph[2 * j + 1][0], ph[2 * j + 1][1] };
            mma_f16(lsum, pa, ONESH2, ONESH2);
#pragma unroll
            for (int bp = 0; bp < 4; bp++) {
                uint32_t b4[4];
                ldm_x4t(b4, bV + ((j * 16 + ra) * APAD + bp * 16 + ca) * 2);
                mma_f16(of[2 * bp],     pa, b4[0], b4[1]);
                mma_f16(of[2 * bp + 1], pa, b4[2], b4[3]);
            }
        }
        l0r = l0r * al0 + lsum[0];
        l1r = l1r * al1 + lsum[2];
    }

    const float inv0 = 1.f / l0r, inv1 = 1.f / l1r;
    const int row0 = qb * 128 + rowbase + g;
#pragma unroll
    for (int nt = 0; nt < 8; nt++) {
        const int col = nt * 8 + 2 * t;
        *(__half2*)&Og[(((size_t)b * SEQ + row0) * NH + h) * HD + col] =
            __floats2half2_rn(of[nt][0] * inv0, of[nt][1] * inv0);
        *(__half2*)&Og[(((size_t)b * SEQ + row0 + 8) * NH + h) * HD + col] =
            __floats2half2_rn(of[nt][2] * inv1, of[nt][3] * inv1);
    }
}

// ---------------------------------------------------------------------------
extern "C" void kernel_launch(void* const* d_in, const int* in_sizes, int n_in,
                              void* d_out, int out_size)
{
    const float* x  = (const float*)d_in[0];
    const float* Wq = (const float*)d_in[1];
    const float* Wk = (const float*)d_in[2];
    const float* Wv = (const float*)d_in[3];
    const float* Wo = (const float*)d_in[4];
    const float* cs = (const float*)d_in[5];
    const float* sn = (const float*)d_in[6];
    float* out = (float*)d_out;

    __half *xh, *qp, *kp, *qh, *kh, *vh, *oh, *wqkvt, *wot;
    cudaGetSymbolAddress((void**)&xh, g_xh);
    cudaGetSymbolAddress((void**)&qp, g_qp);
    cudaGetSymbolAddress((void**)&kp, g_kp);
    cudaGetSymbolAddress((void**)&qh, g_qh);
    cudaGetSymbolAddress((void**)&kh, g_kh);
    cudaGetSymbolAddress((void**)&vh, g_vh);
    cudaGetSymbolAddress((void**)&oh, g_oh);
    cudaGetSymbolAddress((void**)&wqkvt, g_wqkvt);
    cudaGetSymbolAddress((void**)&wot, g_wot);

    cudaFuncSetAttribute(attn_h, cudaFuncAttributeMaxDynamicSharedMemorySize, ATTN_SMEM);
    cudaFuncSetAttribute(hgemm_qkv, cudaFuncAttributeMaxDynamicSharedMemorySize, HGEMM_SMEM);
    cudaFuncSetAttribute(hgemm_f, cudaFuncAttributeMaxDynamicSharedMemorySize, HGEMM_SMEM);

    const int M = MTOT;  // 4096

    prep_kernel<<<NB_F2H + 6144 + 4096, 256>>>(x, xh, Wq, Wk, Wv, wqkvt, Wo, wot);

    hgemm_qkv<<<dim3(24, M / 128), 256, HGEMM_SMEM>>>(xh, wqkvt, qp, kp, vh);

    rope_fused<<<(QTOT4 + KTOT4 + 255) / 256, 256>>>(qp, qh, kp, kh, cs, sn);

    attn_h<<<(SEQ / 128) * NH * BATCH, 256, ATTN_SMEM>>>(qh, kh, vh, oh);

    hgemm_f<<<dim3(DIM / 128, M / 128), 256, HGEMM_SMEM>>>(oh, wot, out, DIM, DIM);
}

// round 15
// speedup vs baseline: 1.5308x; 1.5308x over previous
#include <cuda_runtime.h>
#include <cuda_fp16.h>
#include <cstdint>

#define BATCH 2
#define SEQ 2048
#define DIM 2048
#define NH 32
#define NKV 8
#define HD 64
#define MTOT (BATCH * SEQ)
#define QSCALE 0.18033688011112042f

extern __shared__ char dsmem[];

// Scratch (no cudaMalloc allowed)
__device__ __half g_xh[MTOT * DIM];
__device__ __half g_qp[MTOT * NH * HD];
__device__ __half g_kp[MTOT * NKV * HD];
__device__ __half g_qh[MTOT * NH * HD];
__device__ __half g_kh[MTOT * NKV * HD];
__device__ __half g_vh[MTOT * NKV * HD];
__device__ __half g_oh[MTOT * NH * HD];
__device__ __half g_wqkvt[3072 * DIM];
__device__ __half g_wot[DIM * DIM];

// ---------------------------------------------------------------------------
// helpers
// ---------------------------------------------------------------------------
__device__ __forceinline__ uint32_t smem_u32(const void* p) {
    uint32_t a;
    asm("{ .reg .u64 t; cvta.to.shared.u64 t, %1; cvt.u32.u64 %0, t; }" : "=r"(a) : "l"(p));
    return a;
}

__device__ __forceinline__ void cpa16(uint32_t dst, const void* src) {
    asm volatile("cp.async.cg.shared.global [%0], [%1], 16;" :: "r"(dst), "l"(src) : "memory");
}
#define CP_COMMIT() asm volatile("cp.async.commit_group;" ::: "memory")
#define CP_WAIT1()  asm volatile("cp.async.wait_group 1;" ::: "memory")

__device__ __forceinline__ void ldm_x4(uint32_t r[4], uint32_t addr) {
    asm volatile("ldmatrix.sync.aligned.m8n8.x4.shared.b16 {%0,%1,%2,%3}, [%4];"
                 : "=r"(r[0]), "=r"(r[1]), "=r"(r[2]), "=r"(r[3]) : "r"(addr));
}
__device__ __forceinline__ void ldm_x4t(uint32_t r[4], uint32_t addr) {
    asm volatile("ldmatrix.sync.aligned.m8n8.x4.trans.shared.b16 {%0,%1,%2,%3}, [%4];"
                 : "=r"(r[0]), "=r"(r[1]), "=r"(r[2]), "=r"(r[3]) : "r"(addr));
}

__device__ __forceinline__ void mma_f16(float c[4], const uint32_t a[4],
                                        uint32_t b0, uint32_t b1) {
    asm volatile(
        "mma.sync.aligned.m16n8k16.row.col.f32.f16.f16.f32 "
        "{%0,%1,%2,%3}, {%4,%5,%6,%7}, {%8,%9}, {%0,%1,%2,%3};"
        : "+f"(c[0]), "+f"(c[1]), "+f"(c[2]), "+f"(c[3])
        : "r"(a[0]), "r"(a[1]), "r"(a[2]), "r"(a[3]), "r"(b0), "r"(b1));
}

__device__ __forceinline__ uint32_t ex2h2(float x, float y) {
    __half2 d = __floats2half2_rn(x, y);
    uint32_t e;
    asm("ex2.approx.f16x2 %0, %1;" : "=r"(e) : "r"(*(uint32_t*)&d));
    return e;
}

__device__ __forceinline__ void store2(float* C, size_t off, float x, float y) {
    *(float2*)&C[off] = make_float2(x, y);
}
__device__ __forceinline__ void store2(__half* C, size_t off, float x, float y) {
    *(__half2*)&C[off] = __floats2half2_rn(x, y);
}

// ---------------------------------------------------------------------------
// Fused prep: f2h of x, QKV weight transpose, Wo transpose
// ---------------------------------------------------------------------------
#define NB_F2H (MTOT * DIM / 1024)

__global__ __launch_bounds__(256) void prep_kernel(
    const float* __restrict__ x, __half* __restrict__ xh,
    const float* __restrict__ Wq, const float* __restrict__ Wk,
    const float* __restrict__ Wv, __half* __restrict__ wqkvt,
    const float* __restrict__ Wo, __half* __restrict__ wot)
{
    __shared__ float tbuf[32][33];
    const int bid = blockIdx.x;
    const int tid = threadIdx.x;

    if (bid < NB_F2H) {
        int i = (bid * 256 + tid) * 4;
        float4 v = *(const float4*)&x[i];
        *(__half2*)&xh[i]     = __floats2half2_rn(v.x, v.y);
        *(__half2*)&xh[i + 2] = __floats2half2_rn(v.z, v.w);
        return;
    }

    const int tx = tid & 31, ty = tid >> 5;
    const float* src; __half* dst;
    int srcN, nloc, n0, k0, dstK;

    if (bid < NB_F2H + 6144) {
        const int tb = bid - NB_F2H;
        n0 = (tb % 96) * 32;
        k0 = (tb / 96) * 32;
        if (n0 < 2048)      { src = Wq; srcN = 2048; nloc = n0; }
        else if (n0 < 2560) { src = Wk; srcN = 512;  nloc = n0 - 2048; }
        else                { src = Wv; srcN = 512;  nloc = n0 - 2560; }
        dst = wqkvt; dstK = DIM;
    } else {
        const int tb = bid - NB_F2H - 6144;
        n0 = (tb % 64) * 32;
        k0 = (tb / 64) * 32;
        src = Wo; srcN = DIM; nloc = n0;
        dst = wot; dstK = DIM;
    }

#pragma unroll
    for (int r = ty; r < 32; r += 8)
        tbuf[r][tx] = src[(size_t)(k0 + r) * srcN + nloc + tx];
    __syncthreads();
#pragma unroll
    for (int r = ty; r < 32; r += 8)
        dst[(size_t)(n0 + r) * dstK + k0 + tx] = __float2half(tbuf[tx][r]);
}

// ---------------------------------------------------------------------------
// GEMM core (round-12 proven config: 128x128, BK=32, 3-stage, 2 CTAs/SM)
// ---------------------------------------------------------------------------
#define GPAD 40
#define GBUF (128 * GPAD)
#define STAGES 3
#define HGEMM_SMEM (2 * STAGES * GBUF * 2)   // 61440 B

struct GemmAcc { float a[4][4][4]; };

template <typename EPI>
__device__ __forceinline__ void hgemm_core(
    const __half* Ag0, const __half* Bg0, int K, EPI epi)
{
    __half* Asm = (__half*)dsmem;
    __half* Bsm = Asm + STAGES * GBUF;
    const uint32_t sA = smem_u32(Asm), sB = smem_u32(Bsm);

    const int tid = threadIdx.x, lane = tid & 31, warp = tid >> 5;
    const int wm = warp & 1, wn = warp >> 1;
    const int g = lane >> 2, t = lane & 3;
    const int srow = tid >> 1, sk = (tid & 1) * 16;

    const int ra = (lane & 7) + 8 * ((lane >> 3) & 1);
    const int ca = 8 * (lane >> 4);
    const int rb = (lane & 7) + 8 * (lane >> 4);
    const int cb = 8 * ((lane >> 3) & 1);

    const __half* Ag = Ag0 + (size_t)srow * K + sk;
    const __half* Bg = Bg0 + (size_t)srow * K + sk;
    const uint32_t stOff = (uint32_t)(srow * GPAD + sk) * 2;

    GemmAcc acc;
#pragma unroll
    for (int i = 0; i < 4; i++)
#pragma unroll
        for (int j = 0; j < 4; j++)
#pragma unroll
            for (int c = 0; c < 4; c++) acc.a[i][j][c] = 0.f;

    const int KT = K / 32;
#pragma unroll
    for (int p = 0; p < 2; p++) {
        uint32_t da = sA + p * GBUF * 2 + stOff;
        uint32_t db = sB + p * GBUF * 2 + stOff;
        cpa16(da, Ag + p * 32);  cpa16(da + 16, Ag + p * 32 + 8);
        cpa16(db, Bg + p * 32);  cpa16(db + 16, Bg + p * 32 + 8);
        CP_COMMIT();
    }

    for (int it = 0; it < KT; it++) {
        CP_WAIT1();
        __syncthreads();
        if (it + 2 < KT) {
            const int st = (it + 2) % STAGES;
            uint32_t da = sA + st * GBUF * 2 + stOff;
            uint32_t db = sB + st * GBUF * 2 + stOff;
            cpa16(da, Ag + (it + 2) * 32);  cpa16(da + 16, Ag + (it + 2) * 32 + 8);
            cpa16(db, Bg + (it + 2) * 32);  cpa16(db + 16, Bg + (it + 2) * 32 + 8);
        }
        CP_COMMIT();

        const uint32_t bA = sA + (it % STAGES) * GBUF * 2;
        const uint32_t bB = sB + (it % STAGES) * GBUF * 2;
#pragma unroll
        for (int ks = 0; ks < 2; ks++) {
            const int k0 = ks * 16;
            uint32_t af[4][4];
#pragma unroll
            for (int mt = 0; mt < 4; mt++)
                ldm_x4(af[mt], bA + ((wm * 64 + mt * 16 + ra) * GPAD + k0 + ca) * 2);
#pragma unroll
            for (int bp = 0; bp < 2; bp++) {
                uint32_t b4[4];
                ldm_x4(b4, bB + ((wn * 32 + bp * 16 + rb) * GPAD + k0 + cb) * 2);
#pragma unroll
                for (int mt = 0; mt < 4; mt++) {
                    mma_f16(acc.a[mt][2 * bp],     af[mt], b4[0], b4[1]);
                    mma_f16(acc.a[mt][2 * bp + 1], af[mt], b4[2], b4[3]);
                }
            }
        }
    }
    epi(acc, wm, wn, g, t);
}

// QKV fused projection
__global__ __launch_bounds__(256, 2) void hgemm_qkv(
    const __half* __restrict__ A, const __half* __restrict__ Bt,
    __half* __restrict__ Q, __half* __restrict__ Kc, __half* __restrict__ V)
{
    const int bx = blockIdx.x, by = blockIdx.y;
    __half* Cp; int colbase, stride;
    if (bx < 16)      { Cp = Q;  colbase = bx * 128;        stride = 2048; }
    else if (bx < 20) { Cp = Kc; colbase = (bx - 16) * 128; stride = 512;  }
    else              { Cp = V;  colbase = (bx - 20) * 128; stride = 512;  }
    hgemm_core(A + (size_t)(by * 128) * DIM, Bt + (size_t)(bx * 128) * DIM, DIM,
        [&](const GemmAcc& acc, int wm, int wn, int g, int t) {
#pragma unroll
            for (int mt = 0; mt < 4; mt++) {
                const int row = by * 128 + wm * 64 + mt * 16 + g;
#pragma unroll
                for (int nt = 0; nt < 4; nt++) {
                    const int col = colbase + wn * 32 + nt * 8 + 2 * t;
                    store2(Cp, (size_t)row * stride + col,
                           acc.a[mt][nt][0], acc.a[mt][nt][1]);
                    store2(Cp, (size_t)(row + 8) * stride + col,
                           acc.a[mt][nt][2], acc.a[mt][nt][3]);
                }
            }
        });
}

__global__ __launch_bounds__(256, 2) void hgemm_f(
    const __half* __restrict__ A, const __half* __restrict__ Bt,
    float* __restrict__ C, int N, int K)
{
    const int bx = blockIdx.x, by = blockIdx.y;
    hgemm_core(A + (size_t)(by * 128) * K, Bt + (size_t)(bx * 128) * K, K,
        [&](const GemmAcc& acc, int wm, int wn, int g, int t) {
#pragma unroll
            for (int mt = 0; mt < 4; mt++) {
                const int row = by * 128 + wm * 64 + mt * 16 + g;
#pragma unroll
                for (int nt = 0; nt < 4; nt++) {
                    const int col = bx * 128 + wn * 32 + nt * 8 + 2 * t;
                    store2(C, (size_t)row * N + col, acc.a[mt][nt][0], acc.a[mt][nt][1]);
                    store2(C, (size_t)(row + 8) * N + col, acc.a[mt][nt][2], acc.a[mt][nt][3]);
                }
            }
        });
}

// ---------------------------------------------------------------------------
// Fused RoPE for Q and K
// ---------------------------------------------------------------------------
#define QTOT4 (MTOT * NH * 8)
#define KTOT4 (MTOT * NKV * 8)

__global__ void rope_fused(const __half* __restrict__ qin, __half* __restrict__ qout,
                           const __half* __restrict__ kin, __half* __restrict__ kout,
                           const float* __restrict__ cs, const float* __restrict__ sn)
{
    int idx = blockIdx.x * blockDim.x + threadIdx.x;
    const __half* in; __half* out;
    int nheads; float scale;
    if (idx < QTOT4) {
        in = qin; out = qout; nheads = NH; scale = QSCALE;
    } else {
        idx -= QTOT4;
        if (idx >= KTOT4) return;
        in = kin; out = kout; nheads = NKV; scale = 1.0f;
    }
    const int d4 = (idx & 7) * 4;
    const int rest = idx >> 3;
    const int s = (rest / nheads) % SEQ;
    const size_t base = (size_t)rest * HD;
    uint2 lo2 = *(const uint2*)&in[base + d4];
    uint2 hi2 = *(const uint2*)&in[base + d4 + 32];
    const __half2* lh = (const __half2*)&lo2;
    const __half2* hh = (const __half2*)&hi2;
    float2 l01 = __half22float2(lh[0]), l23 = __half22float2(lh[1]);
    float2 h01 = __half22float2(hh[0]), h23 = __half22float2(hh[1]);
    float4 c0 = *(const float4*)&cs[s * HD + d4];
    float4 s0 = *(const float4*)&sn[s * HD + d4];
    float4 c1 = *(const float4*)&cs[s * HD + d4 + 32];
    float4 s1 = *(const float4*)&sn[s * HD + d4 + 32];
    *(__half2*)&out[base + d4] = __floats2half2_rn(
        (l01.x * c0.x - h01.x * s0.x) * scale, (l01.y * c0.y - h01.y * s0.y) * scale);
    *(__half2*)&out[base + d4 + 2] = __floats2half2_rn(
        (l23.x * c0.z - h23.x * s0.z) * scale, (l23.y * c0.w - h23.y * s0.w) * scale);
    *(__half2*)&out[base + d4 + 32] = __floats2half2_rn(
        (h01.x * c1.x + l01.x * s1.x) * scale, (h01.y * c1.y + l01.y * s1.y) * scale);
    *(__half2*)&out[base + d4 + 34] = __floats2half2_rn(
        (h23.x * c1.z + l23.x * s1.z) * scale, (h23.y * c1.w + l23.y * s1.w) * scale);
}

// ---------------------------------------------------------------------------
// fp16 flash attention: MMA row sums + LPT + fully-masked-chunk skip.
// ---------------------------------------------------------------------------
#define APAD 72
#define KVBUF (64 * APAD)
#define ATTN_SMEM ((128 + 3 * 64 + 3 * 64) * APAD * 2)   // 73728 B
#define ONESH2 0x3C003C00u

__global__ __launch_bounds__(256) void attn_h(
    const __half* __restrict__ Qg, const __half* __restrict__ Kg,
    const __half* __restrict__ Vg, __half* __restrict__ Og)
{
    __half* Qs = (__half*)dsmem;
    __half* Ks = Qs + 128 * APAD;
    __half* Vs = Ks + 3 * KVBUF;
    const uint32_t sQ = smem_u32(Qs), sK = smem_u32(Ks), sV = smem_u32(Vs);

    const int lin = blockIdx.x;
    const int qb = (SEQ / 128 - 1) - (lin >> 6);
    const int h = lin & 31;
    const int b = (lin >> 5) & 1;
    const int kvh = h >> 2;
    const int tid = threadIdx.x;
    const int warp = tid >> 5, lane = tid & 31;
    const int g = lane >> 2, t = lane & 3;
    const int rowbase = warp * 16;

    const int ra = (lane & 7) + 8 * ((lane >> 3) & 1);
    const int ca = 8 * (lane >> 4);
    const int rb = (lane & 7) + 8 * (lane >> 4);
    const int cb = 8 * ((lane >> 3) & 1);

    const int nchunks = 2 * (qb + 1);
    const int svrow = tid >> 2;
    const int svc   = (tid & 3) * 16;
    const uint32_t kvOff = (uint32_t)(svrow * APAD + svc) * 2;
    const size_t gstride = (size_t)64 * NKV * HD;
    const __half* Kgp = Kg + (((size_t)b * SEQ + svrow) * NKV + kvh) * HD + svc;
    const __half* Vgp = Vg + (((size_t)b * SEQ + svrow) * NKV + kvh) * HD + svc;

#pragma unroll
    for (int p = 0; p < 2; p++) {
        uint32_t dk = sK + p * KVBUF * 2 + kvOff;
        uint32_t dv = sV + p * KVBUF * 2 + kvOff;
        cpa16(dk, Kgp + p * gstride);  cpa16(dk + 16, Kgp + p * gstride + 8);
        cpa16(dv, Vgp + p * gstride);  cpa16(dv + 16, Vgp + p * gstride + 8);
        CP_COMMIT();
    }

    {
        const int row = tid & 127;
        const int c0 = (tid >> 7) * 32;
        const __half* src = &Qg[(((size_t)b * SEQ + qb * 128 + row) * NH + h) * HD + c0];
        uint32_t d = sQ + (row * APAD + c0) * 2;
#pragma unroll
        for (int i = 0; i < 4; i++) {
            uint4 v = *(const uint4*)(src + 8 * i);
            asm volatile("st.shared.v4.b32 [%0], {%1,%2,%3,%4};" :: "r"(d + 16 * i),
                         "r"(v.x), "r"(v.y), "r"(v.z), "r"(v.w) : "memory");
        }
    }
    __syncthreads();

    uint32_t qf[4][4];
#pragma unroll
    for (int kt = 0; kt < 4; kt++)
        ldm_x4(qf[kt], sQ + ((rowbase + ra) * APAD + kt * 16 + ca) * 2);

    float m0r = -1e30f, m1r = -1e30f, l0r = 0.f, l1r = 0.f;
    float of[8][4];
#pragma unroll
    for (int nt = 0; nt < 8; nt++)
#pragma unroll
        for (int c = 0; c < 4; c++) of[nt][c] = 0.f;

    // highest q-row this warp owns (global)
    const int warp_qmax = qb * 128 + rowbase + 15;

    for (int kc = 0; kc < nchunks; kc++) {
        CP_WAIT1();
        __syncthreads();
        if (kc + 2 < nchunks) {
            const int st = (kc + 2) % 3;
            uint32_t dk = sK + st * KVBUF * 2 + kvOff;
            uint32_t dv = sV + st * KVBUF * 2 + kvOff;
            cpa16(dk, Kgp + (size_t)(kc + 2) * gstride);
            cpa16(dk + 16, Kgp + (size_t)(kc + 2) * gstride + 8);
            cpa16(dv, Vgp + (size_t)(kc + 2) * gstride);
            cpa16(dv + 16, Vgp + (size_t)(kc + 2) * gstride + 8);
        }
        CP_COMMIT();

        // entire chunk masked for this warp's rows -> skip compute
        if (kc * 64 > warp_qmax) continue;

        const uint32_t bK = sK + (kc % 3) * KVBUF * 2;
        const uint32_t bV = sV + (kc % 3) * KVBUF * 2;

        float sf[8][4];
#pragma unroll
        for (int nt = 0; nt < 8; nt++)
#pragma unroll
            for (int c = 0; c < 4; c++) sf[nt][c] = 0.f;

#pragma unroll
        for (int kt = 0; kt < 4; kt++) {
#pragma unroll
            for (int bp = 0; bp < 4; bp++) {
                uint32_t b4[4];
                ldm_x4(b4, bK + ((bp * 16 + rb) * APAD + kt * 16 + cb) * 2);
                mma_f16(sf[2 * bp],     qf[kt], b4[0], b4[1]);
                mma_f16(sf[2 * bp + 1], qf[kt], b4[2], b4[3]);
            }
        }

        const int qr0 = qb * 128 + rowbase + g;
        const int qr1 = qr0 + 8;
        if (kc * 64 + 63 > qr0) {
#pragma unroll
            for (int nt = 0; nt < 8; nt++) {
                const int kv0 = kc * 64 + nt * 8 + 2 * t;
                if (kv0 > qr0)     sf[nt][0] = -1e30f;
                if (kv0 + 1 > qr0) sf[nt][1] = -1e30f;
                if (kv0 > qr1)     sf[nt][2] = -1e30f;
                if (kv0 + 1 > qr1) sf[nt][3] = -1e30f;
            }
        }

        float mx0 = -1e30f, mx1 = -1e30f;
#pragma unroll
        for (int nt = 0; nt < 8; nt++) {
            mx0 = fmaxf(mx0, fmaxf(sf[nt][0], sf[nt][1]));
            mx1 = fmaxf(mx1, fmaxf(sf[nt][2], sf[nt][3]));
        }
        mx0 = fmaxf(mx0, __shfl_xor_sync(0xffffffffu, mx0, 1));
        mx0 = fmaxf(mx0, __shfl_xor_sync(0xffffffffu, mx0, 2));
        mx1 = fmaxf(mx1, __shfl_xor_sync(0xffffffffu, mx1, 1));
        mx1 = fmaxf(mx1, __shfl_xor_sync(0xffffffffu, mx1, 2));

        const float mn0 = fmaxf(m0r, mx0);
        const float mn1 = fmaxf(m1r, mx1);
        const float al0 = exp2f(m0r - mn0);
        const float al1 = exp2f(m1r - mn1);
        m0r = mn0; m1r = mn1;

        uint32_t ph[8][2];
#pragma unroll
        for (int nt = 0; nt < 8; nt++) {
            ph[nt][0] = ex2h2(sf[nt][0] - mn0, sf[nt][1] - mn0);
            ph[nt][1] = ex2h2(sf[nt][2] - mn1, sf[nt][3] - mn1);
        }

#pragma unroll
        for (int nt = 0; nt < 8; nt++) {
            of[nt][0] *= al0; of[nt][1] *= al0;
            of[nt][2] *= al1; of[nt][3] *= al1;
        }

        float lsum[4] = {0.f, 0.f, 0.f, 0.f};
#pragma unroll
        for (int j = 0; j < 4; j++) {
            uint32_t pa[4] = { ph[2 * j][0], ph[2 * j][1],
                               ph[2 * j + 1][0], ph[2 * j + 1][1] };
            mma_f16(lsum, pa, ONESH2, ONESH2);
#pragma unroll
            for (int bp = 0; bp < 4; bp++) {
                uint32_t b4[4];
                ldm_x4t(b4, bV + ((j * 16 + ra) * APAD + bp * 16 + ca) * 2);
                mma_f16(of[2 * bp],     pa, b4[0], b4[1]);
                mma_f16(of[2 * bp + 1], pa, b4[2], b4[3]);
            }
        }
        l0r = l0r * al0 + lsum[0];
        l1r = l1r * al1 + lsum[2];
    }

    const float inv0 = 1.f / l0r, inv1 = 1.f / l1r;
    const int row0 = qb * 128 + rowbase + g;
#pragma unroll
    for (int nt = 0; nt < 8; nt++) {
        const int col = nt * 8 + 2 * t;
        *(__half2*)&Og[(((size_t)b * SEQ + row0) * NH + h) * HD + col] =
            __floats2half2_rn(of[nt][0] * inv0, of[nt][1] * inv0);
        *(__half2*)&Og[(((size_t)b * SEQ + row0 + 8) * NH + h) * HD + col] =
            __floats2half2_rn(of[nt][2] * inv1, of[nt][3] * inv1);
    }
}

// ---------------------------------------------------------------------------
extern "C" void kernel_launch(void* const* d_in, const int* in_sizes, int n_in,
                              void* d_out, int out_size)
{
    const float* x  = (const float*)d_in[0];
    const float* Wq = (const float*)d_in[1];
    const float* Wk = (const float*)d_in[2];
    const float* Wv = (const float*)d_in[3];
    const float* Wo = (const float*)d_in[4];
    const float* cs = (const float*)d_in[5];
    const float* sn = (const float*)d_in[6];
    float* out = (float*)d_out;

    __half *xh, *qp, *kp, *qh, *kh, *vh, *oh, *wqkvt, *wot;
    cudaGetSymbolAddress((void**)&xh, g_xh);
    cudaGetSymbolAddress((void**)&qp, g_qp);
    cudaGetSymbolAddress((void**)&kp, g_kp);
    cudaGetSymbolAddress((void**)&qh, g_qh);
    cudaGetSymbolAddress((void**)&kh, g_kh);
    cudaGetSymbolAddress((void**)&vh, g_vh);
    cudaGetSymbolAddress((void**)&oh, g_oh);
    cudaGetSymbolAddress((void**)&wqkvt, g_wqkvt);
    cudaGetSymbolAddress((void**)&wot, g_wot);

    cudaFuncSetAttribute(attn_h, cudaFuncAttributeMaxDynamicSharedMemorySize, ATTN_SMEM);
    cudaFuncSetAttribute(hgemm_qkv, cudaFuncAttributeMaxDynamicSharedMemorySize, HGEMM_SMEM);
    cudaFuncSetAttribute(hgemm_f, cudaFuncAttributeMaxDynamicSharedMemorySize, HGEMM_SMEM);

    const int M = MTOT;  // 4096

    prep_kernel<<<NB_F2H + 6144 + 4096, 256>>>(x, xh, Wq, Wk, Wv, wqkvt, Wo, wot);

    hgemm_qkv<<<dim3(24, M / 128), 256, HGEMM_SMEM>>>(xh, wqkvt, qp, kp, vh);

    rope_fused<<<(QTOT4 + KTOT4 + 255) / 256, 256>>>(qp, qh, kp, kh, cs, sn);

    attn_h<<<(SEQ / 128) * NH * BATCH, 256, ATTN_SMEM>>>(qh, kh, vh, oh);

    hgemm_f<<<dim3(DIM / 128, M / 128), 256, HGEMM_SMEM>>>(oh, wot, out, DIM, DIM);
}

// round 16
// speedup vs baseline: 1.5404x; 1.0062x over previous
#include <cuda_runtime.h>
#include <cuda_fp16.h>
#include <cstdint>

#define BATCH 2
#define SEQ 2048
#define DIM 2048
#define NH 32
#define NKV 8
#define HD 64
#define MTOT (BATCH * SEQ)
#define QSCALE 0.18033688011112042f

extern __shared__ char dsmem[];

// Scratch (no cudaMalloc allowed)
__device__ __half g_xh[MTOT * DIM];
__device__ __half g_qp[MTOT * NH * HD];
__device__ __half g_kp[MTOT * NKV * HD];
__device__ __half g_qh[MTOT * NH * HD];
__device__ __half g_kh[MTOT * NKV * HD];
__device__ __half g_vh[MTOT * NKV * HD];
__device__ __half g_oh[MTOT * NH * HD];
__device__ __half g_wqkvt[3072 * DIM];
__device__ __half g_wot[DIM * DIM];

// ---------------------------------------------------------------------------
// helpers
// ---------------------------------------------------------------------------
__device__ __forceinline__ uint32_t smem_u32(const void* p) {
    uint32_t a;
    asm("{ .reg .u64 t; cvta.to.shared.u64 t, %1; cvt.u32.u64 %0, t; }" : "=r"(a) : "l"(p));
    return a;
}

__device__ __forceinline__ void cpa16(uint32_t dst, const void* src) {
    asm volatile("cp.async.cg.shared.global [%0], [%1], 16;" :: "r"(dst), "l"(src) : "memory");
}
#define CP_COMMIT() asm volatile("cp.async.commit_group;" ::: "memory")
#define CP_WAIT0()  asm volatile("cp.async.wait_group 0;" ::: "memory")
#define CP_WAIT1()  asm volatile("cp.async.wait_group 1;" ::: "memory")

__device__ __forceinline__ void ldm_x4(uint32_t r[4], uint32_t addr) {
    asm volatile("ldmatrix.sync.aligned.m8n8.x4.shared.b16 {%0,%1,%2,%3}, [%4];"
                 : "=r"(r[0]), "=r"(r[1]), "=r"(r[2]), "=r"(r[3]) : "r"(addr));
}
__device__ __forceinline__ void ldm_x4t(uint32_t r[4], uint32_t addr) {
    asm volatile("ldmatrix.sync.aligned.m8n8.x4.trans.shared.b16 {%0,%1,%2,%3}, [%4];"
                 : "=r"(r[0]), "=r"(r[1]), "=r"(r[2]), "=r"(r[3]) : "r"(addr));
}

__device__ __forceinline__ void mma_f16(float c[4], const uint32_t a[4],
                                        uint32_t b0, uint32_t b1) {
    asm volatile(
        "mma.sync.aligned.m16n8k16.row.col.f32.f16.f16.f32 "
        "{%0,%1,%2,%3}, {%4,%5,%6,%7}, {%8,%9}, {%0,%1,%2,%3};"
        : "+f"(c[0]), "+f"(c[1]), "+f"(c[2]), "+f"(c[3])
        : "r"(a[0]), "r"(a[1]), "r"(a[2]), "r"(a[3]), "r"(b0), "r"(b1));
}

__device__ __forceinline__ uint32_t ex2h2(float x, float y) {
    __half2 d = __floats2half2_rn(x, y);
    uint32_t e;
    asm("ex2.approx.f16x2 %0, %1;" : "=r"(e) : "r"(*(uint32_t*)&d));
    return e;
}

__device__ __forceinline__ void store2(float* C, size_t off, float x, float y) {
    *(float2*)&C[off] = make_float2(x, y);
}
__device__ __forceinline__ void store2(__half* C, size_t off, float x, float y) {
    *(__half2*)&C[off] = __floats2half2_rn(x, y);
}

// ---------------------------------------------------------------------------
// Fused prep: f2h of x, QKV weight transpose, Wo transpose
// ---------------------------------------------------------------------------
#define NB_F2H (MTOT * DIM / 1024)

__global__ __launch_bounds__(256) void prep_kernel(
    const float* __restrict__ x, __half* __restrict__ xh,
    const float* __restrict__ Wq, const float* __restrict__ Wk,
    const float* __restrict__ Wv, __half* __restrict__ wqkvt,
    const float* __restrict__ Wo, __half* __restrict__ wot)
{
    __shared__ float tbuf[32][33];
    const int bid = blockIdx.x;
    const int tid = threadIdx.x;

    if (bid < NB_F2H) {
        int i = (bid * 256 + tid) * 4;
        float4 v = *(const float4*)&x[i];
        *(__half2*)&xh[i]     = __floats2half2_rn(v.x, v.y);
        *(__half2*)&xh[i + 2] = __floats2half2_rn(v.z, v.w);
        return;
    }

    const int tx = tid & 31, ty = tid >> 5;
    const float* src; __half* dst;
    int srcN, nloc, n0, k0, dstK;

    if (bid < NB_F2H + 6144) {
        const int tb = bid - NB_F2H;
        n0 = (tb % 96) * 32;
        k0 = (tb / 96) * 32;
        if (n0 < 2048)      { src = Wq; srcN = 2048; nloc = n0; }
        else if (n0 < 2560) { src = Wk; srcN = 512;  nloc = n0 - 2048; }
        else                { src = Wv; srcN = 512;  nloc = n0 - 2560; }
        dst = wqkvt; dstK = DIM;
    } else {
        const int tb = bid - NB_F2H - 6144;
        n0 = (tb % 64) * 32;
        k0 = (tb / 64) * 32;
        src = Wo; srcN = DIM; nloc = n0;
        dst = wot; dstK = DIM;
    }

#pragma unroll
    for (int r = ty; r < 32; r += 8)
        tbuf[r][tx] = src[(size_t)(k0 + r) * srcN + nloc + tx];
    __syncthreads();
#pragma unroll
    for (int r = ty; r < 32; r += 8)
        dst[(size_t)(n0 + r) * dstK + k0 + tx] = __float2half(tbuf[tx][r]);
}

// ---------------------------------------------------------------------------
// GEMM core (round-12 proven config: 128x128, BK=32, 3-stage, 2 CTAs/SM)
// ---------------------------------------------------------------------------
#define GPAD 40
#define GBUF (128 * GPAD)
#define STAGES 3
#define HGEMM_SMEM (2 * STAGES * GBUF * 2)   // 61440 B

struct GemmAcc { float a[4][4][4]; };

template <typename EPI>
__device__ __forceinline__ void hgemm_core(
    const __half* Ag0, const __half* Bg0, int K, EPI epi)
{
    __half* Asm = (__half*)dsmem;
    __half* Bsm = Asm + STAGES * GBUF;
    const uint32_t sA = smem_u32(Asm), sB = smem_u32(Bsm);

    const int tid = threadIdx.x, lane = tid & 31, warp = tid >> 5;
    const int wm = warp & 1, wn = warp >> 1;
    const int g = lane >> 2, t = lane & 3;
    const int srow = tid >> 1, sk = (tid & 1) * 16;

    const int ra = (lane & 7) + 8 * ((lane >> 3) & 1);
    const int ca = 8 * (lane >> 4);
    const int rb = (lane & 7) + 8 * (lane >> 4);
    const int cb = 8 * ((lane >> 3) & 1);

    const __half* Ag = Ag0 + (size_t)srow * K + sk;
    const __half* Bg = Bg0 + (size_t)srow * K + sk;
    const uint32_t stOff = (uint32_t)(srow * GPAD + sk) * 2;

    GemmAcc acc;
#pragma unroll
    for (int i = 0; i < 4; i++)
#pragma unroll
        for (int j = 0; j < 4; j++)
#pragma unroll
            for (int c = 0; c < 4; c++) acc.a[i][j][c] = 0.f;

    const int KT = K / 32;
#pragma unroll
    for (int p = 0; p < 2; p++) {
        uint32_t da = sA + p * GBUF * 2 + stOff;
        uint32_t db = sB + p * GBUF * 2 + stOff;
        cpa16(da, Ag + p * 32);  cpa16(da + 16, Ag + p * 32 + 8);
        cpa16(db, Bg + p * 32);  cpa16(db + 16, Bg + p * 32 + 8);
        CP_COMMIT();
    }

    for (int it = 0; it < KT; it++) {
        CP_WAIT1();
        __syncthreads();
        if (it + 2 < KT) {
            const int st = (it + 2) % STAGES;
            uint32_t da = sA + st * GBUF * 2 + stOff;
            uint32_t db = sB + st * GBUF * 2 + stOff;
            cpa16(da, Ag + (it + 2) * 32);  cpa16(da + 16, Ag + (it + 2) * 32 + 8);
            cpa16(db, Bg + (it + 2) * 32);  cpa16(db + 16, Bg + (it + 2) * 32 + 8);
        }
        CP_COMMIT();

        const uint32_t bA = sA + (it % STAGES) * GBUF * 2;
        const uint32_t bB = sB + (it % STAGES) * GBUF * 2;
#pragma unroll
        for (int ks = 0; ks < 2; ks++) {
            const int k0 = ks * 16;
            uint32_t af[4][4];
#pragma unroll
            for (int mt = 0; mt < 4; mt++)
                ldm_x4(af[mt], bA + ((wm * 64 + mt * 16 + ra) * GPAD + k0 + ca) * 2);
#pragma unroll
            for (int bp = 0; bp < 2; bp++) {
                uint32_t b4[4];
                ldm_x4(b4, bB + ((wn * 32 + bp * 16 + rb) * GPAD + k0 + cb) * 2);
#pragma unroll
                for (int mt = 0; mt < 4; mt++) {
                    mma_f16(acc.a[mt][2 * bp],     af[mt], b4[0], b4[1]);
                    mma_f16(acc.a[mt][2 * bp + 1], af[mt], b4[2], b4[3]);
                }
            }
        }
    }
    epi(acc, wm, wn, g, t);
}

// QKV fused projection
__global__ __launch_bounds__(256, 2) void hgemm_qkv(
    const __half* __restrict__ A, const __half* __restrict__ Bt,
    __half* __restrict__ Q, __half* __restrict__ Kc, __half* __restrict__ V)
{
    const int bx = blockIdx.x, by = blockIdx.y;
    __half* Cp; int colbase, stride;
    if (bx < 16)      { Cp = Q;  colbase = bx * 128;        stride = 2048; }
    else if (bx < 20) { Cp = Kc; colbase = (bx - 16) * 128; stride = 512;  }
    else              { Cp = V;  colbase = (bx - 20) * 128; stride = 512;  }
    hgemm_core(A + (size_t)(by * 128) * DIM, Bt + (size_t)(bx * 128) * DIM, DIM,
        [&](const GemmAcc& acc, int wm, int wn, int g, int t) {
#pragma unroll
            for (int mt = 0; mt < 4; mt++) {
                const int row = by * 128 + wm * 64 + mt * 16 + g;
#pragma unroll
                for (int nt = 0; nt < 4; nt++) {
                    const int col = colbase + wn * 32 + nt * 8 + 2 * t;
                    store2(Cp, (size_t)row * stride + col,
                           acc.a[mt][nt][0], acc.a[mt][nt][1]);
                    store2(Cp, (size_t)(row + 8) * stride + col,
                           acc.a[mt][nt][2], acc.a[mt][nt][3]);
                }
            }
        });
}

__global__ __launch_bounds__(256, 2) void hgemm_f(
    const __half* __restrict__ A, const __half* __restrict__ Bt,
    float* __restrict__ C, int N, int K)
{
    const int bx = blockIdx.x, by = blockIdx.y;
    hgemm_core(A + (size_t)(by * 128) * K, Bt + (size_t)(bx * 128) * K, K,
        [&](const GemmAcc& acc, int wm, int wn, int g, int t) {
#pragma unroll
            for (int mt = 0; mt < 4; mt++) {
                const int row = by * 128 + wm * 64 + mt * 16 + g;
#pragma unroll
                for (int nt = 0; nt < 4; nt++) {
                    const int col = bx * 128 + wn * 32 + nt * 8 + 2 * t;
                    store2(C, (size_t)row * N + col, acc.a[mt][nt][0], acc.a[mt][nt][1]);
                    store2(C, (size_t)(row + 8) * N + col, acc.a[mt][nt][2], acc.a[mt][nt][3]);
                }
            }
        });
}

// ---------------------------------------------------------------------------
// Fused RoPE for Q and K
// ---------------------------------------------------------------------------
#define QTOT4 (MTOT * NH * 8)
#define KTOT4 (MTOT * NKV * 8)

__global__ void rope_fused(const __half* __restrict__ qin, __half* __restrict__ qout,
                           const __half* __restrict__ kin, __half* __restrict__ kout,
                           const float* __restrict__ cs, const float* __restrict__ sn)
{
    int idx = blockIdx.x * blockDim.x + threadIdx.x;
    const __half* in; __half* out;
    int nheads; float scale;
    if (idx < QTOT4) {
        in = qin; out = qout; nheads = NH; scale = QSCALE;
    } else {
        idx -= QTOT4;
        if (idx >= KTOT4) return;
        in = kin; out = kout; nheads = NKV; scale = 1.0f;
    }
    const int d4 = (idx & 7) * 4;
    const int rest = idx >> 3;
    const int s = (rest / nheads) % SEQ;
    const size_t base = (size_t)rest * HD;
    uint2 lo2 = *(const uint2*)&in[base + d4];
    uint2 hi2 = *(const uint2*)&in[base + d4 + 32];
    const __half2* lh = (const __half2*)&lo2;
    const __half2* hh = (const __half2*)&hi2;
    float2 l01 = __half22float2(lh[0]), l23 = __half22float2(lh[1]);
    float2 h01 = __half22float2(hh[0]), h23 = __half22float2(hh[1]);
    float4 c0 = *(const float4*)&cs[s * HD + d4];
    float4 s0 = *(const float4*)&sn[s * HD + d4];
    float4 c1 = *(const float4*)&cs[s * HD + d4 + 32];
    float4 s1 = *(const float4*)&sn[s * HD + d4 + 32];
    *(__half2*)&out[base + d4] = __floats2half2_rn(
        (l01.x * c0.x - h01.x * s0.x) * scale, (l01.y * c0.y - h01.y * s0.y) * scale);
    *(__half2*)&out[base + d4 + 2] = __floats2half2_rn(
        (l23.x * c0.z - h23.x * s0.z) * scale, (l23.y * c0.w - h23.y * s0.w) * scale);
    *(__half2*)&out[base + d4 + 32] = __floats2half2_rn(
        (h01.x * c1.x + l01.x * s1.x) * scale, (h01.y * c1.y + l01.y * s1.y) * scale);
    *(__half2*)&out[base + d4 + 34] = __floats2half2_rn(
        (h23.x * c1.z + l23.x * s1.z) * scale, (h23.y * c1.w + l23.y * s1.w) * scale);
}

// ---------------------------------------------------------------------------
// fp16 flash attention: MMA row sums + LPT + masked skip + 2-chunk barrier
// windows (4 KV stages) so warps drift and fill each other's softmax lulls.
// ---------------------------------------------------------------------------
#define APAD 72
#define KVBUF (64 * APAD)
#define KVSTG 4
#define ATTN_SMEM ((128 + KVSTG * 64 * 2) * APAD * 2)   // 92160 B
#define ONESH2 0x3C003C00u

__global__ __launch_bounds__(256) void attn_h(
    const __half* __restrict__ Qg, const __half* __restrict__ Kg,
    const __half* __restrict__ Vg, __half* __restrict__ Og)
{
    __half* Qs = (__half*)dsmem;
    __half* Ks = Qs + 128 * APAD;
    __half* Vs = Ks + KVSTG * KVBUF;
    const uint32_t sQ = smem_u32(Qs), sK = smem_u32(Ks), sV = smem_u32(Vs);

    const int lin = blockIdx.x;
    const int qb = (SEQ / 128 - 1) - (lin >> 6);
    const int h = lin & 31;
    const int b = (lin >> 5) & 1;
    const int kvh = h >> 2;
    const int tid = threadIdx.x;
    const int warp = tid >> 5, lane = tid & 31;
    const int g = lane >> 2, t = lane & 3;
    const int rowbase = warp * 16;

    const int ra = (lane & 7) + 8 * ((lane >> 3) & 1);
    const int ca = 8 * (lane >> 4);
    const int rb = (lane & 7) + 8 * (lane >> 4);
    const int cb = 8 * ((lane >> 3) & 1);

    const int nchunks = 2 * (qb + 1);   // always even
    const int svrow = tid >> 2;
    const int svc   = (tid & 3) * 16;
    const uint32_t kvOff = (uint32_t)(svrow * APAD + svc) * 2;
    const size_t gstride = (size_t)64 * NKV * HD;
    const __half* Kgp = Kg + (((size_t)b * SEQ + svrow) * NKV + kvh) * HD + svc;
    const __half* Vgp = Vg + (((size_t)b * SEQ + svrow) * NKV + kvh) * HD + svc;

    // prologue: chunks 0, 1
#pragma unroll
    for (int p = 0; p < 2; p++) {
        uint32_t dk = sK + p * KVBUF * 2 + kvOff;
        uint32_t dv = sV + p * KVBUF * 2 + kvOff;
        cpa16(dk, Kgp + p * gstride);  cpa16(dk + 16, Kgp + p * gstride + 8);
        cpa16(dv, Vgp + p * gstride);  cpa16(dv + 16, Vgp + p * gstride + 8);
        CP_COMMIT();
    }

    {
        const int row = tid & 127;
        const int c0 = (tid >> 7) * 32;
        const __half* src = &Qg[(((size_t)b * SEQ + qb * 128 + row) * NH + h) * HD + c0];
        uint32_t d = sQ + (row * APAD + c0) * 2;
#pragma unroll
        for (int i = 0; i < 4; i++) {
            uint4 v = *(const uint4*)(src + 8 * i);
            asm volatile("st.shared.v4.b32 [%0], {%1,%2,%3,%4};" :: "r"(d + 16 * i),
                         "r"(v.x), "r"(v.y), "r"(v.z), "r"(v.w) : "memory");
        }
    }
    __syncthreads();

    uint32_t qf[4][4];
#pragma unroll
    for (int kt = 0; kt < 4; kt++)
        ldm_x4(qf[kt], sQ + ((rowbase + ra) * APAD + kt * 16 + ca) * 2);

    float m0r = -1e30f, m1r = -1e30f, l0r = 0.f, l1r = 0.f;
    float of[8][4];
#pragma unroll
    for (int nt = 0; nt < 8; nt++)
#pragma unroll
        for (int c = 0; c < 4; c++) of[nt][c] = 0.f;

    const int warp_qmax = qb * 128 + rowbase + 15;

    for (int w = 0; w < nchunks; w += 2) {
        CP_WAIT0();          // chunks w, w+1 resident
        __syncthreads();     // previous window's reads done; publish data

        // prefetch chunks w+2, w+3 (stages freed by previous window)
        if (w + 2 < nchunks) {
            const int st = (w + 2) & (KVSTG - 1);
            uint32_t dk = sK + st * KVBUF * 2 + kvOff;
            uint32_t dv = sV + st * KVBUF * 2 + kvOff;
            cpa16(dk, Kgp + (size_t)(w + 2) * gstride);
            cpa16(dk + 16, Kgp + (size_t)(w + 2) * gstride + 8);
            cpa16(dv, Vgp + (size_t)(w + 2) * gstride);
            cpa16(dv + 16, Vgp + (size_t)(w + 2) * gstride + 8);
            CP_COMMIT();
        }
        if (w + 3 < nchunks) {
            const int st = (w + 3) & (KVSTG - 1);
            uint32_t dk = sK + st * KVBUF * 2 + kvOff;
            uint32_t dv = sV + st * KVBUF * 2 + kvOff;
            cpa16(dk, Kgp + (size_t)(w + 3) * gstride);
            cpa16(dk + 16, Kgp + (size_t)(w + 3) * gstride + 8);
            cpa16(dv, Vgp + (size_t)(w + 3) * gstride);
            cpa16(dv + 16, Vgp + (size_t)(w + 3) * gstride + 8);
            CP_COMMIT();
        }

#pragma unroll
        for (int sub = 0; sub < 2; sub++) {
            const int kc = w + sub;
            if (kc * 64 > warp_qmax) continue;   // fully masked for this warp

            const uint32_t bK = sK + (kc & (KVSTG - 1)) * KVBUF * 2;
            const uint32_t bV = sV + (kc & (KVSTG - 1)) * KVBUF * 2;

            // ---- S = Q K^T ----
            float sf[8][4];
#pragma unroll
            for (int nt = 0; nt < 8; nt++)
#pragma unroll
                for (int c = 0; c < 4; c++) sf[nt][c] = 0.f;

#pragma unroll
            for (int kt = 0; kt < 4; kt++) {
#pragma unroll
                for (int bp = 0; bp < 4; bp++) {
                    uint32_t b4[4];
                    ldm_x4(b4, bK + ((bp * 16 + rb) * APAD + kt * 16 + cb) * 2);
                    mma_f16(sf[2 * bp],     qf[kt], b4[0], b4[1]);
                    mma_f16(sf[2 * bp + 1], qf[kt], b4[2], b4[3]);
                }
            }

            // ---- causal mask ----
            const int qr0 = qb * 128 + rowbase + g;
            const int qr1 = qr0 + 8;
            if (kc * 64 + 63 > qr0) {
#pragma unroll
                for (int nt = 0; nt < 8; nt++) {
                    const int kv0 = kc * 64 + nt * 8 + 2 * t;
                    if (kv0 > qr0)     sf[nt][0] = -1e30f;
                    if (kv0 + 1 > qr0) sf[nt][1] = -1e30f;
                    if (kv0 > qr1)     sf[nt][2] = -1e30f;
                    if (kv0 + 1 > qr1) sf[nt][3] = -1e30f;
                }
            }

            // ---- online softmax: max reduce ----
            float mx0 = -1e30f, mx1 = -1e30f;
#pragma unroll
            for (int nt = 0; nt < 8; nt++) {
                mx0 = fmaxf(mx0, fmaxf(sf[nt][0], sf[nt][1]));
                mx1 = fmaxf(mx1, fmaxf(sf[nt][2], sf[nt][3]));
            }
            mx0 = fmaxf(mx0, __shfl_xor_sync(0xffffffffu, mx0, 1));
            mx0 = fmaxf(mx0, __shfl_xor_sync(0xffffffffu, mx0, 2));
            mx1 = fmaxf(mx1, __shfl_xor_sync(0xffffffffu, mx1, 1));
            mx1 = fmaxf(mx1, __shfl_xor_sync(0xffffffffu, mx1, 2));

            const float mn0 = fmaxf(m0r, mx0);
            const float mn1 = fmaxf(m1r, mx1);
            const float al0 = exp2f(m0r - mn0);
            const float al1 = exp2f(m1r - mn1);
            m0r = mn0; m1r = mn1;

            // ---- exp via f16x2 MUFU (results are PV A-fragments) ----
            uint32_t ph[8][2];
#pragma unroll
            for (int nt = 0; nt < 8; nt++) {
                ph[nt][0] = ex2h2(sf[nt][0] - mn0, sf[nt][1] - mn0);
                ph[nt][1] = ex2h2(sf[nt][2] - mn1, sf[nt][3] - mn1);
            }

            // ---- rescale O ----
#pragma unroll
            for (int nt = 0; nt < 8; nt++) {
                of[nt][0] *= al0; of[nt][1] *= al0;
                of[nt][2] *= al1; of[nt][3] *= al1;
            }

            // ---- O += P @ V, row sums via MMA with all-ones B ----
            float lsum[4] = {0.f, 0.f, 0.f, 0.f};
#pragma unroll
            for (int j = 0; j < 4; j++) {
                uint32_t pa[4] = { ph[2 * j][0], ph[2 * j][1],
                                   ph[2 * j + 1][0], ph[2 * j + 1][1] };
                mma_f16(lsum, pa, ONESH2, ONESH2);
#pragma unroll
                for (int bp = 0; bp < 4; bp++) {
                    uint32_t b4[4];
                    ldm_x4t(b4, bV + ((j * 16 + ra) * APAD + bp * 16 + ca) * 2);
                    mma_f16(of[2 * bp],     pa, b4[0], b4[1]);
                    mma_f16(of[2 * bp + 1], pa, b4[2], b4[3]);
                }
            }
            l0r = l0r * al0 + lsum[0];
            l1r = l1r * al1 + lsum[2];
        }
    }

    // ---- epilogue ----
    const float inv0 = 1.f / l0r, inv1 = 1.f / l1r;
    const int row0 = qb * 128 + rowbase + g;
#pragma unroll
    for (int nt = 0; nt < 8; nt++) {
        const int col = nt * 8 + 2 * t;
        *(__half2*)&Og[(((size_t)b * SEQ + row0) * NH + h) * HD + col] =
            __floats2half2_rn(of[nt][0] * inv0, of[nt][1] * inv0);
        *(__half2*)&Og[(((size_t)b * SEQ + row0 + 8) * NH + h) * HD + col] =
            __floats2half2_rn(of[nt][2] * inv1, of[nt][3] * inv1);
    }
}

// ---------------------------------------------------------------------------
extern "C" void kernel_launch(void* const* d_in, const int* in_sizes, int n_in,
                              void* d_out, int out_size)
{
    const float* x  = (const float*)d_in[0];
    const float* Wq = (const float*)d_in[1];
    const float* Wk = (const float*)d_in[2];
    const float* Wv = (const float*)d_in[3];
    const float* Wo = (const float*)d_in[4];
    const float* cs = (const float*)d_in[5];
    const float* sn = (const float*)d_in[6];
    float* out = (float*)d_out;

    __half *xh, *qp, *kp, *qh, *kh, *vh, *oh, *wqkvt, *wot;
    cudaGetSymbolAddress((void**)&xh, g_xh);
    cudaGetSymbolAddress((void**)&qp, g_qp);
    cudaGetSymbolAddress((void**)&kp, g_kp);
    cudaGetSymbolAddress((void**)&qh, g_qh);
    cudaGetSymbolAddress((void**)&kh, g_kh);
    cudaGetSymbolAddress((void**)&vh, g_vh);
    cudaGetSymbolAddress((void**)&oh, g_oh);
    cudaGetSymbolAddress((void**)&wqkvt, g_wqkvt);
    cudaGetSymbolAddress((void**)&wot, g_wot);

    cudaFuncSetAttribute(attn_h, cudaFuncAttributeMaxDynamicSharedMemorySize, ATTN_SMEM);
    cudaFuncSetAttribute(hgemm_qkv, cudaFuncAttributeMaxDynamicSharedMemorySize, HGEMM_SMEM);
    cudaFuncSetAttribute(hgemm_f, cudaFuncAttributeMaxDynamicSharedMemorySize, HGEMM_SMEM);

    const int M = MTOT;  // 4096

    prep_kernel<<<NB_F2H + 6144 + 4096, 256>>>(x, xh, Wq, Wk, Wv, wqkvt, Wo, wot);

    hgemm_qkv<<<dim3(24, M / 128), 256, HGEMM_SMEM>>>(xh, wqkvt, qp, kp, vh);

    rope_fused<<<(QTOT4 + KTOT4 + 255) / 256, 256>>>(qp, qh, kp, kh, cs, sn);

    attn_h<<<(SEQ / 128) * NH * BATCH, 256, ATTN_SMEM>>>(qh, kh, vh, oh);

    hgemm_f<<<dim3(DIM / 128, M / 128), 256, HGEMM_SMEM>>>(oh, wot, out, DIM, DIM);
}

// round 17
// speedup vs baseline: 1.6240x; 1.0543x over previous
#include <cuda_runtime.h>
#include <cuda_fp16.h>
#include <cstdint>

#define BATCH 2
#define SEQ 2048
#define DIM 2048
#define NH 32
#define NKV 8
#define HD 64
#define MTOT (BATCH * SEQ)
#define QSCALE 0.18033688011112042f

extern __shared__ char dsmem[];

// Scratch (no cudaMalloc allowed)
__device__ __half g_xh[MTOT * DIM];
__device__ __half g_qp[MTOT * NH * HD];
__device__ __half g_kp[MTOT * NKV * HD];
__device__ __half g_qh[MTOT * NH * HD];
__device__ __half g_kh[MTOT * NKV * HD];
__device__ __half g_vh[MTOT * NKV * HD];
__device__ __half g_oh[MTOT * NH * HD];
__device__ __half g_wqkvt[3072 * DIM];
__device__ __half g_wot[DIM * DIM];

// ---------------------------------------------------------------------------
// helpers
// ---------------------------------------------------------------------------
__device__ __forceinline__ uint32_t smem_u32(const void* p) {
    uint32_t a;
    asm("{ .reg .u64 t; cvta.to.shared.u64 t, %1; cvt.u32.u64 %0, t; }" : "=r"(a) : "l"(p));
    return a;
}

__device__ __forceinline__ void cpa16(uint32_t dst, const void* src) {
    asm volatile("cp.async.cg.shared.global [%0], [%1], 16;" :: "r"(dst), "l"(src) : "memory");
}
#define CP_COMMIT() asm volatile("cp.async.commit_group;" ::: "memory")
#define CP_WAIT0()  asm volatile("cp.async.wait_group 0;" ::: "memory")
#define CP_WAIT1()  asm volatile("cp.async.wait_group 1;" ::: "memory")

__device__ __forceinline__ void ldm_x4(uint32_t r[4], uint32_t addr) {
    asm volatile("ldmatrix.sync.aligned.m8n8.x4.shared.b16 {%0,%1,%2,%3}, [%4];"
                 : "=r"(r[0]), "=r"(r[1]), "=r"(r[2]), "=r"(r[3]) : "r"(addr));
}
__device__ __forceinline__ void ldm_x4t(uint32_t r[4], uint32_t addr) {
    asm volatile("ldmatrix.sync.aligned.m8n8.x4.trans.shared.b16 {%0,%1,%2,%3}, [%4];"
                 : "=r"(r[0]), "=r"(r[1]), "=r"(r[2]), "=r"(r[3]) : "r"(addr));
}

__device__ __forceinline__ void mma_f16(float c[4], const uint32_t a[4],
                                        uint32_t b0, uint32_t b1) {
    asm volatile(
        "mma.sync.aligned.m16n8k16.row.col.f32.f16.f16.f32 "
        "{%0,%1,%2,%3}, {%4,%5,%6,%7}, {%8,%9}, {%0,%1,%2,%3};"
        : "+f"(c[0]), "+f"(c[1]), "+f"(c[2]), "+f"(c[3])
        : "r"(a[0]), "r"(a[1]), "r"(a[2]), "r"(a[3]), "r"(b0), "r"(b1));
}

__device__ __forceinline__ uint32_t ex2h2(float x, float y) {
    __half2 d = __floats2half2_rn(x, y);
    uint32_t e;
    asm("ex2.approx.f16x2 %0, %1;" : "=r"(e) : "r"(*(uint32_t*)&d));
    return e;
}

__device__ __forceinline__ void store2(float* C, size_t off, float x, float y) {
    *(float2*)&C[off] = make_float2(x, y);
}
__device__ __forceinline__ void store2(__half* C, size_t off, float x, float y) {
    *(__half2*)&C[off] = __floats2half2_rn(x, y);
}

// ---------------------------------------------------------------------------
// Fused prep: f2h of x, QKV weight transpose, Wo transpose
// ---------------------------------------------------------------------------
#define NB_F2H (MTOT * DIM / 1024)

__global__ __launch_bounds__(256) void prep_kernel(
    const float* __restrict__ x, __half* __restrict__ xh,
    const float* __restrict__ Wq, const float* __restrict__ Wk,
    const float* __restrict__ Wv, __half* __restrict__ wqkvt,
    const float* __restrict__ Wo, __half* __restrict__ wot)
{
    __shared__ float tbuf[32][33];
    const int bid = blockIdx.x;
    const int tid = threadIdx.x;

    if (bid < NB_F2H) {
        int i = (bid * 256 + tid) * 4;
        float4 v = *(const float4*)&x[i];
        *(__half2*)&xh[i]     = __floats2half2_rn(v.x, v.y);
        *(__half2*)&xh[i + 2] = __floats2half2_rn(v.z, v.w);
        return;
    }

    const int tx = tid & 31, ty = tid >> 5;
    const float* src; __half* dst;
    int srcN, nloc, n0, k0, dstK;

    if (bid < NB_F2H + 6144) {
        const int tb = bid - NB_F2H;
        n0 = (tb % 96) * 32;
        k0 = (tb / 96) * 32;
        if (n0 < 2048)      { src = Wq; srcN = 2048; nloc = n0; }
        else if (n0 < 2560) { src = Wk; srcN = 512;  nloc = n0 - 2048; }
        else                { src = Wv; srcN = 512;  nloc = n0 - 2560; }
        dst = wqkvt; dstK = DIM;
    } else {
        const int tb = bid - NB_F2H - 6144;
        n0 = (tb % 64) * 32;
        k0 = (tb / 64) * 32;
        src = Wo; srcN = DIM; nloc = n0;
        dst = wot; dstK = DIM;
    }

#pragma unroll
    for (int r = ty; r < 32; r += 8)
        tbuf[r][tx] = src[(size_t)(k0 + r) * srcN + nloc + tx];
    __syncthreads();
#pragma unroll
    for (int r = ty; r < 32; r += 8)
        dst[(size_t)(n0 + r) * dstK + k0 + tx] = __float2half(tbuf[tx][r]);
}

// ---------------------------------------------------------------------------
// GEMM core: 128x128 CTA tile, BK=32, 3-stage cp.async, 512 threads,
// 16 warps (4m x 4n), warp tile 32x32. 2 CTAs/SM -> 32 warps/SM.
// ---------------------------------------------------------------------------
#define GPAD 40
#define GBUF (128 * GPAD)
#define STAGES 3
#define HGEMM_SMEM (2 * STAGES * GBUF * 2)   // 61440 B

struct GemmAcc { float a[2][4][4]; };

template <typename EPI>
__device__ __forceinline__ void hgemm_core(
    const __half* Ag0, const __half* Bg0, int K, EPI epi)
{
    __half* Asm = (__half*)dsmem;
    __half* Bsm = Asm + STAGES * GBUF;
    const uint32_t sA = smem_u32(Asm), sB = smem_u32(Bsm);

    const int tid = threadIdx.x, lane = tid & 31, warp = tid >> 5;
    const int wm = warp & 3, wn = warp >> 2;   // 4 x 4 warp grid
    const int g = lane >> 2, t = lane & 3;

    const int ra = (lane & 7) + 8 * ((lane >> 3) & 1);
    const int ca = 8 * (lane >> 4);
    const int rb = (lane & 7) + 8 * (lane >> 4);
    const int cb = 8 * ((lane >> 3) & 1);

    // staging: 128 rows x 32 halves per operand; 512 threads -> 1 cpa16 each
    const int srow = tid >> 2, sk = (tid & 3) * 8;
    const __half* Ag = Ag0 + (size_t)srow * K + sk;
    const __half* Bg = Bg0 + (size_t)srow * K + sk;
    const uint32_t stOff = (uint32_t)(srow * GPAD + sk) * 2;

    GemmAcc acc;
#pragma unroll
    for (int i = 0; i < 2; i++)
#pragma unroll
        for (int j = 0; j < 4; j++)
#pragma unroll
            for (int c = 0; c < 4; c++) acc.a[i][j][c] = 0.f;

    const int KT = K / 32;
#pragma unroll
    for (int p = 0; p < 2; p++) {
        cpa16(sA + p * GBUF * 2 + stOff, Ag + p * 32);
        cpa16(sB + p * GBUF * 2 + stOff, Bg + p * 32);
        CP_COMMIT();
    }

    for (int it = 0; it < KT; it++) {
        CP_WAIT1();
        __syncthreads();
        if (it + 2 < KT) {
            const int st = (it + 2) % STAGES;
            cpa16(sA + st * GBUF * 2 + stOff, Ag + (it + 2) * 32);
            cpa16(sB + st * GBUF * 2 + stOff, Bg + (it + 2) * 32);
        }
        CP_COMMIT();

        const uint32_t bA = sA + (it % STAGES) * GBUF * 2;
        const uint32_t bB = sB + (it % STAGES) * GBUF * 2;
#pragma unroll
        for (int ks = 0; ks < 2; ks++) {
            const int k0 = ks * 16;
            uint32_t af[2][4];
#pragma unroll
            for (int mt = 0; mt < 2; mt++)
                ldm_x4(af[mt], bA + ((wm * 32 + mt * 16 + ra) * GPAD + k0 + ca) * 2);
#pragma unroll
            for (int bp = 0; bp < 2; bp++) {
                uint32_t b4[4];
                ldm_x4(b4, bB + ((wn * 32 + bp * 16 + rb) * GPAD + k0 + cb) * 2);
#pragma unroll
                for (int mt = 0; mt < 2; mt++) {
                    mma_f16(acc.a[mt][2 * bp],     af[mt], b4[0], b4[1]);
                    mma_f16(acc.a[mt][2 * bp + 1], af[mt], b4[2], b4[3]);
                }
            }
        }
    }
    epi(acc, wm, wn, g, t);
}

// QKV fused projection
__global__ __launch_bounds__(512, 2) void hgemm_qkv(
    const __half* __restrict__ A, const __half* __restrict__ Bt,
    __half* __restrict__ Q, __half* __restrict__ Kc, __half* __restrict__ V)
{
    const int bx = blockIdx.x, by = blockIdx.y;
    __half* Cp; int colbase, stride;
    if (bx < 16)      { Cp = Q;  colbase = bx * 128;        stride = 2048; }
    else if (bx < 20) { Cp = Kc; colbase = (bx - 16) * 128; stride = 512;  }
    else              { Cp = V;  colbase = (bx - 20) * 128; stride = 512;  }
    hgemm_core(A + (size_t)(by * 128) * DIM, Bt + (size_t)(bx * 128) * DIM, DIM,
        [&](const GemmAcc& acc, int wm, int wn, int g, int t) {
#pragma unroll
            for (int mt = 0; mt < 2; mt++) {
                const int row = by * 128 + wm * 32 + mt * 16 + g;
#pragma unroll
                for (int nt = 0; nt < 4; nt++) {
                    const int col = colbase + wn * 32 + nt * 8 + 2 * t;
                    store2(Cp, (size_t)row * stride + col,
                           acc.a[mt][nt][0], acc.a[mt][nt][1]);
                    store2(Cp, (size_t)(row + 8) * stride + col,
                           acc.a[mt][nt][2], acc.a[mt][nt][3]);
                }
            }
        });
}

__global__ __launch_bounds__(512, 2) void hgemm_f(
    const __half* __restrict__ A, const __half* __restrict__ Bt,
    float* __restrict__ C, int N, int K)
{
    const int bx = blockIdx.x, by = blockIdx.y;
    hgemm_core(A + (size_t)(by * 128) * K, Bt + (size_t)(bx * 128) * K, K,
        [&](const GemmAcc& acc, int wm, int wn, int g, int t) {
#pragma unroll
            for (int mt = 0; mt < 2; mt++) {
                const int row = by * 128 + wm * 32 + mt * 16 + g;
#pragma unroll
                for (int nt = 0; nt < 4; nt++) {
                    const int col = bx * 128 + wn * 32 + nt * 8 + 2 * t;
                    store2(C, (size_t)row * N + col, acc.a[mt][nt][0], acc.a[mt][nt][1]);
                    store2(C, (size_t)(row + 8) * N + col, acc.a[mt][nt][2], acc.a[mt][nt][3]);
                }
            }
        });
}

// ---------------------------------------------------------------------------
// Fused RoPE for Q and K
// ---------------------------------------------------------------------------
#define QTOT4 (MTOT * NH * 8)
#define KTOT4 (MTOT * NKV * 8)

__global__ void rope_fused(const __half* __restrict__ qin, __half* __restrict__ qout,
                           const __half* __restrict__ kin, __half* __restrict__ kout,
                           const float* __restrict__ cs, const float* __restrict__ sn)
{
    int idx = blockIdx.x * blockDim.x + threadIdx.x;
    const __half* in; __half* out;
    int nheads; float scale;
    if (idx < QTOT4) {
        in = qin; out = qout; nheads = NH; scale = QSCALE;
    } else {
        idx -= QTOT4;
        if (idx >= KTOT4) return;
        in = kin; out = kout; nheads = NKV; scale = 1.0f;
    }
    const int d4 = (idx & 7) * 4;
    const int rest = idx >> 3;
    const int s = (rest / nheads) % SEQ;
    const size_t base = (size_t)rest * HD;
    uint2 lo2 = *(const uint2*)&in[base + d4];
    uint2 hi2 = *(const uint2*)&in[base + d4 + 32];
    const __half2* lh = (const __half2*)&lo2;
    const __half2* hh = (const __half2*)&hi2;
    float2 l01 = __half22float2(lh[0]), l23 = __half22float2(lh[1]);
    float2 h01 = __half22float2(hh[0]), h23 = __half22float2(hh[1]);
    float4 c0 = *(const float4*)&cs[s * HD + d4];
    float4 s0 = *(const float4*)&sn[s * HD + d4];
    float4 c1 = *(const float4*)&cs[s * HD + d4 + 32];
    float4 s1 = *(const float4*)&sn[s * HD + d4 + 32];
    *(__half2*)&out[base + d4] = __floats2half2_rn(
        (l01.x * c0.x - h01.x * s0.x) * scale, (l01.y * c0.y - h01.y * s0.y) * scale);
    *(__half2*)&out[base + d4 + 2] = __floats2half2_rn(
        (l23.x * c0.z - h23.x * s0.z) * scale, (l23.y * c0.w - h23.y * s0.w) * scale);
    *(__half2*)&out[base + d4 + 32] = __floats2half2_rn(
        (h01.x * c1.x + l01.x * s1.x) * scale, (h01.y * c1.y + l01.y * s1.y) * scale);
    *(__half2*)&out[base + d4 + 34] = __floats2half2_rn(
        (h23.x * c1.z + l23.x * s1.z) * scale, (h23.y * c1.w + l23.y * s1.w) * scale);
}

// ---------------------------------------------------------------------------
// fp16 flash attention (round-16 version: MMA row sums + LPT + masked skip +
// 2-chunk barrier windows)
// ---------------------------------------------------------------------------
#define APAD 72
#define KVBUF (64 * APAD)
#define KVSTG 4
#define ATTN_SMEM ((128 + KVSTG * 64 * 2) * APAD * 2)   // 92160 B
#define ONESH2 0x3C003C00u

__global__ __launch_bounds__(256) void attn_h(
    const __half* __restrict__ Qg, const __half* __restrict__ Kg,
    const __half* __restrict__ Vg, __half* __restrict__ Og)
{
    __half* Qs = (__half*)dsmem;
    __half* Ks = Qs + 128 * APAD;
    __half* Vs = Ks + KVSTG * KVBUF;
    const uint32_t sQ = smem_u32(Qs), sK = smem_u32(Ks), sV = smem_u32(Vs);

    const int lin = blockIdx.x;
    const int qb = (SEQ / 128 - 1) - (lin >> 6);
    const int h = lin & 31;
    const int b = (lin >> 5) & 1;
    const int kvh = h >> 2;
    const int tid = threadIdx.x;
    const int warp = tid >> 5, lane = tid & 31;
    const int g = lane >> 2, t = lane & 3;
    const int rowbase = warp * 16;

    const int ra = (lane & 7) + 8 * ((lane >> 3) & 1);
    const int ca = 8 * (lane >> 4);
    const int rb = (lane & 7) + 8 * (lane >> 4);
    const int cb = 8 * ((lane >> 3) & 1);

    const int nchunks = 2 * (qb + 1);
    const int svrow = tid >> 2;
    const int svc   = (tid & 3) * 16;
    const uint32_t kvOff = (uint32_t)(svrow * APAD + svc) * 2;
    const size_t gstride = (size_t)64 * NKV * HD;
    const __half* Kgp = Kg + (((size_t)b * SEQ + svrow) * NKV + kvh) * HD + svc;
    const __half* Vgp = Vg + (((size_t)b * SEQ + svrow) * NKV + kvh) * HD + svc;

#pragma unroll
    for (int p = 0; p < 2; p++) {
        uint32_t dk = sK + p * KVBUF * 2 + kvOff;
        uint32_t dv = sV + p * KVBUF * 2 + kvOff;
        cpa16(dk, Kgp + p * gstride);  cpa16(dk + 16, Kgp + p * gstride + 8);
        cpa16(dv, Vgp + p * gstride);  cpa16(dv + 16, Vgp + p * gstride + 8);
        CP_COMMIT();
    }

    {
        const int row = tid & 127;
        const int c0 = (tid >> 7) * 32;
        const __half* src = &Qg[(((size_t)b * SEQ + qb * 128 + row) * NH + h) * HD + c0];
        uint32_t d = sQ + (row * APAD + c0) * 2;
#pragma unroll
        for (int i = 0; i < 4; i++) {
            uint4 v = *(const uint4*)(src + 8 * i);
            asm volatile("st.shared.v4.b32 [%0], {%1,%2,%3,%4};" :: "r"(d + 16 * i),
                         "r"(v.x), "r"(v.y), "r"(v.z), "r"(v.w) : "memory");
        }
    }
    __syncthreads();

    uint32_t qf[4][4];
#pragma unroll
    for (int kt = 0; kt < 4; kt++)
        ldm_x4(qf[kt], sQ + ((rowbase + ra) * APAD + kt * 16 + ca) * 2);

    float m0r = -1e30f, m1r = -1e30f, l0r = 0.f, l1r = 0.f;
    float of[8][4];
#pragma unroll
    for (int nt = 0; nt < 8; nt++)
#pragma unroll
        for (int c = 0; c < 4; c++) of[nt][c] = 0.f;

    const int warp_qmax = qb * 128 + rowbase + 15;

    for (int w = 0; w < nchunks; w += 2) {
        CP_WAIT0();
        __syncthreads();

        if (w + 2 < nchunks) {
            const int st = (w + 2) & (KVSTG - 1);
            uint32_t dk = sK + st * KVBUF * 2 + kvOff;
            uint32_t dv = sV + st * KVBUF * 2 + kvOff;
            cpa16(dk, Kgp + (size_t)(w + 2) * gstride);
            cpa16(dk + 16, Kgp + (size_t)(w + 2) * gstride + 8);
            cpa16(dv, Vgp + (size_t)(w + 2) * gstride);
            cpa16(dv + 16, Vgp + (size_t)(w + 2) * gstride + 8);
            CP_COMMIT();
        }
        if (w + 3 < nchunks) {
            const int st = (w + 3) & (KVSTG - 1);
            uint32_t dk = sK + st * KVBUF * 2 + kvOff;
            uint32_t dv = sV + st * KVBUF * 2 + kvOff;
            cpa16(dk, Kgp + (size_t)(w + 3) * gstride);
            cpa16(dk + 16, Kgp + (size_t)(w + 3) * gstride + 8);
            cpa16(dv, Vgp + (size_t)(w + 3) * gstride);
            cpa16(dv + 16, Vgp + (size_t)(w + 3) * gstride + 8);
            CP_COMMIT();
        }

#pragma unroll
        for (int sub = 0; sub < 2; sub++) {
            const int kc = w + sub;
            if (kc * 64 > warp_qmax) continue;

            const uint32_t bK = sK + (kc & (KVSTG - 1)) * KVBUF * 2;
            const uint32_t bV = sV + (kc & (KVSTG - 1)) * KVBUF * 2;

            float sf[8][4];
#pragma unroll
            for (int nt = 0; nt < 8; nt++)
#pragma unroll
                for (int c = 0; c < 4; c++) sf[nt][c] = 0.f;

#pragma unroll
            for (int kt = 0; kt < 4; kt++) {
#pragma unroll
                for (int bp = 0; bp < 4; bp++) {
                    uint32_t b4[4];
                    ldm_x4(b4, bK + ((bp * 16 + rb) * APAD + kt * 16 + cb) * 2);
                    mma_f16(sf[2 * bp],     qf[kt], b4[0], b4[1]);
                    mma_f16(sf[2 * bp + 1], qf[kt], b4[2], b4[3]);
                }
            }

            const int qr0 = qb * 128 + rowbase + g;
            const int qr1 = qr0 + 8;
            if (kc * 64 + 63 > qr0) {
#pragma unroll
                for (int nt = 0; nt < 8; nt++) {
                    const int kv0 = kc * 64 + nt * 8 + 2 * t;
                    if (kv0 > qr0)     sf[nt][0] = -1e30f;
                    if (kv0 + 1 > qr0) sf[nt][1] = -1e30f;
                    if (kv0 > qr1)     sf[nt][2] = -1e30f;
                    if (kv0 + 1 > qr1) sf[nt][3] = -1e30f;
                }
            }

            float mx0 = -1e30f, mx1 = -1e30f;
#pragma unroll
            for (int nt = 0; nt < 8; nt++) {
                mx0 = fmaxf(mx0, fmaxf(sf[nt][0], sf[nt][1]));
                mx1 = fmaxf(mx1, fmaxf(sf[nt][2], sf[nt][3]));
            }
            mx0 = fmaxf(mx0, __shfl_xor_sync(0xffffffffu, mx0, 1));
            mx0 = fmaxf(mx0, __shfl_xor_sync(0xffffffffu, mx0, 2));
            mx1 = fmaxf(mx1, __shfl_xor_sync(0xffffffffu, mx1, 1));
            mx1 = fmaxf(mx1, __shfl_xor_sync(0xffffffffu, mx1, 2));

            const float mn0 = fmaxf(m0r, mx0);
            const float mn1 = fmaxf(m1r, mx1);
            const float al0 = exp2f(m0r - mn0);
            const float al1 = exp2f(m1r - mn1);
            m0r = mn0; m1r = mn1;

            uint32_t ph[8][2];
#pragma unroll
            for (int nt = 0; nt < 8; nt++) {
                ph[nt][0] = ex2h2(sf[nt][0] - mn0, sf[nt][1] - mn0);
                ph[nt][1] = ex2h2(sf[nt][2] - mn1, sf[nt][3] - mn1);
            }

#pragma unroll
            for (int nt = 0; nt < 8; nt++) {
                of[nt][0] *= al0; of[nt][1] *= al0;
                of[nt][2] *= al1; of[nt][3] *= al1;
            }

            float lsum[4] = {0.f, 0.f, 0.f, 0.f};
#pragma unroll
            for (int j = 0; j < 4; j++) {
                uint32_t pa[4] = { ph[2 * j][0], ph[2 * j][1],
                                   ph[2 * j + 1][0], ph[2 * j + 1][1] };
                mma_f16(lsum, pa, ONESH2, ONESH2);
#pragma unroll
                for (int bp = 0; bp < 4; bp++) {
                    uint32_t b4[4];
                    ldm_x4t(b4, bV + ((j * 16 + ra) * APAD + bp * 16 + ca) * 2);
                    mma_f16(of[2 * bp],     pa, b4[0], b4[1]);
                    mma_f16(of[2 * bp + 1], pa, b4[2], b4[3]);
                }
            }
            l0r = l0r * al0 + lsum[0];
            l1r = l1r * al1 + lsum[2];
        }
    }

    const float inv0 = 1.f / l0r, inv1 = 1.f / l1r;
    const int row0 = qb * 128 + rowbase + g;
#pragma unroll
    for (int nt = 0; nt < 8; nt++) {
        const int col = nt * 8 + 2 * t;
        *(__half2*)&Og[(((size_t)b * SEQ + row0) * NH + h) * HD + col] =
            __floats2half2_rn(of[nt][0] * inv0, of[nt][1] * inv0);
        *(__half2*)&Og[(((size_t)b * SEQ + row0 + 8) * NH + h) * HD + col] =
            __floats2half2_rn(of[nt][2] * inv1, of[nt][3] * inv1);
    }
}

// ---------------------------------------------------------------------------
extern "C" void kernel_launch(void* const* d_in, const int* in_sizes, int n_in,
                              void* d_out, int out_size)
{
    const float* x  = (const float*)d_in[0];
    const float* Wq = (const float*)d_in[1];
    const float* Wk = (const float*)d_in[2];
    const float* Wv = (const float*)d_in[3];
    const float* Wo = (const float*)d_in[4];
    const float* cs = (const float*)d_in[5];
    const float* sn = (const float*)d_in[6];
    float* out = (float*)d_out;

    __half *xh, *qp, *kp, *qh, *kh, *vh, *oh, *wqkvt, *wot;
    cudaGetSymbolAddress((void**)&xh, g_xh);
    cudaGetSymbolAddress((void**)&qp, g_qp);
    cudaGetSymbolAddress((void**)&kp, g_kp);
    cudaGetSymbolAddress((void**)&qh, g_qh);
    cudaGetSymbolAddress((void**)&kh, g_kh);
    cudaGetSymbolAddress((void**)&vh, g_vh);
    cudaGetSymbolAddress((void**)&oh, g_oh);
    cudaGetSymbolAddress((void**)&wqkvt, g_wqkvt);
    cudaGetSymbolAddress((void**)&wot, g_wot);

    cudaFuncSetAttribute(attn_h, cudaFuncAttributeMaxDynamicSharedMemorySize, ATTN_SMEM);
    cudaFuncSetAttribute(hgemm_qkv, cudaFuncAttributeMaxDynamicSharedMemorySize, HGEMM_SMEM);
    cudaFuncSetAttribute(hgemm_f, cudaFuncAttributeMaxDynamicSharedMemorySize, HGEMM_SMEM);

    const int M = MTOT;  // 4096

    prep_kernel<<<NB_F2H + 6144 + 4096, 256>>>(x, xh, Wq, Wk, Wv, wqkvt, Wo, wot);

    hgemm_qkv<<<dim3(24, M / 128), 512, HGEMM_SMEM>>>(xh, wqkvt, qp, kp, vh);

    rope_fused<<<(QTOT4 + KTOT4 + 255) / 256, 256>>>(qp, qh, kp, kh, cs, sn);

    attn_h<<<(SEQ / 128) * NH * BATCH, 256, ATTN_SMEM>>>(qh, kh, vh, oh);

    hgemm_f<<<dim3(DIM / 128, M / 128), 512, HGEMM_SMEM>>>(oh, wot, out, DIM, DIM);
}